// round 1
// baseline (speedup 1.0000x reference)
#include <cuda_runtime.h>
#include <math.h>

#define BB 2
#define S1D 64
#define S2D 64
#define S3D 40
#define CHW 64
#define MMD 23
#define TTD 8
#define NPTS (BB*S1D*S2D*S3D)   // 327680
#define NLAY 4

// ---------------- device scratch (static, allocation-free) ----------------
__device__ float g_x [NPTS*CHW];            // activations, [b][n1][n2][n3][c]
__device__ float g_s1[NPTS*CHW];            // spectral-conv output
__device__ float g_Ar[BB*S1D*S2D*TTD*CHW];  // [b][n1][n2][kz][c]
__device__ float g_Ai[BB*S1D*S2D*TTD*CHW];
__device__ float g_Br[BB*MMD*S2D*TTD*CHW];  // [b][ky][n2][kz][c] (fwd) / [b][n1][kx][kz][c] (inv)
__device__ float g_Bi[BB*MMD*S2D*TTD*CHW];
__device__ float g_Xr[BB*MMD*MMD*TTD*CHW];  // [b][ky][kx][kz][c]
__device__ float g_Xi[BB*MMD*MMD*TTD*CHW];
__device__ float g_Yr[BB*MMD*MMD*TTD*CHW];
__device__ float g_Yi[BB*MMD*MMD*TTD*CHW];
__device__ float g_wlc[NLAY*12*TTD*CHW*CHW];     // [l][a*8+kz][i*64+o]
__device__ float g_wlr[NLAY*11*11*TTD*CHW*CHW];  // [l][(p*11+q)*8+kz][i*64+o]

// ---------------- weight transpose: [l][io][m] -> [l][m][io] ----------------
__global__ void transpose_k(const float* __restrict__ src, int rows, int cols, int which) {
    __shared__ float tile[32][33];
    float* dst = which ? g_wlr : g_wlc;
    int l = blockIdx.z;
    const float* s = src + (size_t)l * rows * cols;
    float* d = dst + (size_t)l * rows * cols;
    int c0 = blockIdx.x * 32, r0 = blockIdx.y * 32;
    int tx = threadIdx.x;
    for (int dy = threadIdx.y; dy < 32; dy += 8) {
        int r = r0 + dy, c = c0 + tx;
        if (r < rows && c < cols) tile[dy][tx] = s[(size_t)r * cols + c];
    }
    __syncthreads();
    for (int dy = threadIdx.y; dy < 32; dy += 8) {
        int c = c0 + dy, r = r0 + tx;
        if (r < rows && c < cols) d[(size_t)c * rows + r] = tile[tx][dy];
    }
}

// ---------------- lift: x(.,10) + grid(3) -> 64 channels ----------------
__global__ void lift_k(const float* __restrict__ xin, const float* __restrict__ pw,
                       const float* __restrict__ pb) {
    int e = blockIdx.x * 256 + threadIdx.x;
    if (e >= NPTS * CHW) return;
    int c = e & 63;
    int p = e >> 6;
    int n3 = p % S3D;
    int r = p / S3D;
    int n2 = r & 63; r >>= 6;
    int n1 = r & 63;
    const float* xp = xin + (size_t)p * 10;
    const float* w = pw + c * 13;
    float acc = pb[c];
#pragma unroll
    for (int i = 0; i < 10; i++) acc += w[i] * xp[i];
    acc += w[10] * (n1 * (1.0f / 63.0f));
    acc += w[11] * (n2 * (1.0f / 63.0f));
    acc += w[12] * (n3 * (1.0f / 39.0f));
    g_x[e] = acc;
}

// ---------------- forward z-DFT: real 40 -> complex 8 ----------------
__global__ void fwdz_k() {
    __shared__ float sx[S3D][CHW];
    __shared__ float cz[TTD][S3D], szt[TTD][S3D];
    int blk = blockIdx.x;            // b*4096 + n1*64 + n2
    int tid = threadIdx.x;
    const float* xp = g_x + (size_t)blk * (S3D * CHW);
    for (int i = tid; i < S3D * CHW; i += 256) sx[i >> 6][i & 63] = xp[i];
    for (int i = tid; i < TTD * S3D; i += 256) {
        int k = i / S3D, n = i % S3D;
        float s, c;
        sincospif((float)((2 * k * n) % 80) * (1.0f / 40.0f), &s, &c);
        cz[k][n] = c; szt[k][n] = s;
    }
    __syncthreads();
    int c = tid & 63, kq = tid >> 6;
    int k0 = kq, k1 = kq + 4;
    float a0r = 0, a0i = 0, a1r = 0, a1i = 0;
#pragma unroll 8
    for (int n = 0; n < S3D; n++) {
        float v = sx[n][c];
        a0r += v * cz[k0][n]; a0i -= v * szt[k0][n];
        a1r += v * cz[k1][n]; a1i -= v * szt[k1][n];
    }
    size_t base = (size_t)blk * (TTD * CHW);
    g_Ar[base + k0 * CHW + c] = a0r; g_Ai[base + k0 * CHW + c] = a0i;
    g_Ar[base + k1 * CHW + c] = a1r; g_Ai[base + k1 * CHW + c] = a1i;
}

// ---------------- forward y-DFT: n1 (64) -> ky (23), freq ky-11 ----------------
__global__ void fwdy_k() {
    __shared__ float Sr[S1D][CHW], Si[S1D][CHW];
    __shared__ float cy[MMD][S1D], sy[MMD][S1D];
    int blk = blockIdx.x;            // ((b*S2+n2)*8+kz)
    int kz = blk % TTD, n2 = (blk / TTD) % S2D, b = blk / (TTD * S2D);
    int tid = threadIdx.x;
    for (int i = tid; i < S1D * CHW; i += 256) {
        int n1 = i >> 6, c = i & 63;
        size_t g = ((((size_t)b * S1D + n1) * S2D + n2) * TTD + kz) * CHW + c;
        Sr[n1][c] = g_Ar[g]; Si[n1][c] = g_Ai[g];
    }
    for (int i = tid; i < MMD * S1D; i += 256) {
        int ky = i >> 6, n = i & 63;
        int t = ((ky - 11) * n) & 63;
        float s, c; sincospif((float)t * (1.0f / 32.0f), &s, &c);
        cy[ky][n] = c; sy[ky][n] = s;
    }
    __syncthreads();
    int c = tid & 63, q = tid >> 6;
    for (int ky = q; ky < MMD; ky += 4) {
        float ar = 0, ai = 0;
#pragma unroll 8
        for (int n = 0; n < S1D; n++) {
            float fr = cy[ky][n], fi = sy[ky][n];
            float xr = Sr[n][c], xi = Si[n][c];
            ar += xr * fr + xi * fi;
            ai += xi * fr - xr * fi;
        }
        size_t g = ((((size_t)b * MMD + ky) * S2D + n2) * TTD + kz) * CHW + c;
        g_Br[g] = ar; g_Bi[g] = ai;
    }
}

// ---------------- forward x-DFT: n2 (64) -> kx (23) ----------------
__global__ void fwdx_k() {
    __shared__ float Sr[S2D][CHW], Si[S2D][CHW];
    __shared__ float cy[MMD][S2D], sy[MMD][S2D];
    int blk = blockIdx.x;            // ((b*23+ky)*8+kz)
    int kz = blk % TTD, ky = (blk / TTD) % MMD, b = blk / (TTD * MMD);
    int tid = threadIdx.x;
    for (int i = tid; i < S2D * CHW; i += 256) {
        int n2 = i >> 6, c = i & 63;
        size_t g = ((((size_t)b * MMD + ky) * S2D + n2) * TTD + kz) * CHW + c;
        Sr[n2][c] = g_Br[g]; Si[n2][c] = g_Bi[g];
    }
    for (int i = tid; i < MMD * S2D; i += 256) {
        int kx = i >> 6, n = i & 63;
        int t = ((kx - 11) * n) & 63;
        float s, c; sincospif((float)t * (1.0f / 32.0f), &s, &c);
        cy[kx][n] = c; sy[kx][n] = s;
    }
    __syncthreads();
    int c = tid & 63, q = tid >> 6;
    for (int kx = q; kx < MMD; kx += 4) {
        float ar = 0, ai = 0;
#pragma unroll 8
        for (int n = 0; n < S2D; n++) {
            float fr = cy[kx][n], fi = sy[kx][n];
            float xr = Sr[n][c], xi = Si[n][c];
            ar += xr * fr + xi * fi;
            ai += xi * fr - xr * fi;
        }
        size_t g = ((((size_t)b * MMD + ky) * MMD + kx) * TTD + kz) * CHW + c;
        g_Xr[g] = ar; g_Xi[g] = ai;
    }
}

// --------- mode -> (sel, a, b) mapping replicating _spectral_weights ---------
__device__ __forceinline__ void map_mode(int y, int x, int& sel, int& ia, int& ib) {
    int yy, s;
    if (x >= 11) { yy = y; s = x - 11; }
    else         { yy = 22 - y; s = 11 - x; }
    int r, t;
    if (yy < 12) {
        if (s == 0) { sel = 0; ia = 11 - yy; ib = 0; return; }
        r = s - 1; t = 11 - yy;
    } else { r = yy - 12; t = s; }
    if (t == 0) { sel = 0; ia = r + 1; ib = 0; }
    else        { sel = 1; ia = r;     ib = t - 1; }
}

// ---------------- per-mode 64x64 channel mix (complex * real W) ----------------
__global__ void mix_k(int l) {
    __shared__ float sw[CHW * CHW];
    __shared__ float xr[BB][CHW], xi[BB][CHW];
    int m = blockIdx.x;
    int kz = m % TTD, x = (m / TTD) % MMD, y = m / (TTD * MMD);
    int sel, ia, ib;
    map_mode(y, x, sel, ia, ib);
    const float* wp;
    if (sel == 0) wp = g_wlc + (((size_t)l * 12 + ia) * TTD + kz) * (CHW * CHW);
    else          wp = g_wlr + (((size_t)l * 121 + ia * 11 + ib) * TTD + kz) * (CHW * CHW);
    int tid = threadIdx.x;   // 128
    for (int i = tid; i < CHW * CHW; i += 128) sw[i] = wp[i];
    for (int i = tid; i < BB * CHW; i += 128) {
        int b = i >> 6, c = i & 63;
        size_t g = ((((size_t)b * MMD + y) * MMD + x) * TTD + kz) * CHW + c;
        xr[b][c] = g_Xr[g]; xi[b][c] = g_Xi[g];
    }
    __syncthreads();
    int o = tid & 63, b = tid >> 6;
    float ar = 0, ai = 0;
#pragma unroll 8
    for (int i = 0; i < CHW; i++) {
        float w = sw[i * CHW + o];
        ar += xr[b][i] * w;
        ai += xi[b][i] * w;
    }
    size_t g = ((((size_t)b * MMD + y) * MMD + x) * TTD + kz) * CHW + o;
    g_Yr[g] = ar; g_Yi[g] = ai;
}

// ---------------- inverse y: ky (23) -> n1 (64), exp(+i...) ----------------
__global__ void invy_k() {
    __shared__ float Sr[MMD][CHW], Si[MMD][CHW];
    __shared__ float cy[MMD][S1D], sy[MMD][S1D];
    int blk = blockIdx.x;            // ((b*23+kx)*8+kz)
    int kz = blk % TTD, kx = (blk / TTD) % MMD, b = blk / (TTD * MMD);
    int tid = threadIdx.x;
    for (int i = tid; i < MMD * CHW; i += 256) {
        int ky = i >> 6, c = i & 63;
        size_t g = ((((size_t)b * MMD + ky) * MMD + kx) * TTD + kz) * CHW + c;
        Sr[ky][c] = g_Yr[g]; Si[ky][c] = g_Yi[g];
    }
    for (int i = tid; i < MMD * S1D; i += 256) {
        int ky = i >> 6, n = i & 63;
        int t = ((ky - 11) * n) & 63;
        float s, c; sincospif((float)t * (1.0f / 32.0f), &s, &c);
        cy[ky][n] = c; sy[ky][n] = s;
    }
    __syncthreads();
    int c = tid & 63, q = tid >> 6;
    for (int n1 = q; n1 < S1D; n1 += 4) {
        float ar = 0, ai = 0;
#pragma unroll
        for (int ky = 0; ky < MMD; ky++) {
            float fr = cy[ky][n1], fi = sy[ky][n1];
            float xr = Sr[ky][c], xi = Si[ky][c];
            ar += xr * fr - xi * fi;
            ai += xr * fi + xi * fr;
        }
        size_t g = ((((size_t)b * S1D + n1) * MMD + kx) * TTD + kz) * CHW + c;
        g_Br[g] = ar; g_Bi[g] = ai;
    }
}

// ---------------- inverse x: kx (23) -> n2 (64) ----------------
__global__ void invx_k() {
    __shared__ float Sr[MMD][CHW], Si[MMD][CHW];
    __shared__ float cy[MMD][S2D], sy[MMD][S2D];
    int blk = blockIdx.x;            // ((b*64+n1)*8+kz)
    int kz = blk % TTD, n1 = (blk / TTD) % S1D, b = blk / (TTD * S1D);
    int tid = threadIdx.x;
    for (int i = tid; i < MMD * CHW; i += 256) {
        int kx = i >> 6, c = i & 63;
        size_t g = ((((size_t)b * S1D + n1) * MMD + kx) * TTD + kz) * CHW + c;
        Sr[kx][c] = g_Br[g]; Si[kx][c] = g_Bi[g];
    }
    for (int i = tid; i < MMD * S2D; i += 256) {
        int kx = i >> 6, n = i & 63;
        int t = ((kx - 11) * n) & 63;
        float s, c; sincospif((float)t * (1.0f / 32.0f), &s, &c);
        cy[kx][n] = c; sy[kx][n] = s;
    }
    __syncthreads();
    int c = tid & 63, q = tid >> 6;
    for (int n2 = q; n2 < S2D; n2 += 4) {
        float ar = 0, ai = 0;
#pragma unroll
        for (int kx = 0; kx < MMD; kx++) {
            float fr = cy[kx][n2], fi = sy[kx][n2];
            float xr = Sr[kx][c], xi = Si[kx][c];
            ar += xr * fr - xi * fi;
            ai += xr * fi + xi * fr;
        }
        size_t g = (((size_t)b * S1D + n1) * S2D + n2) * (TTD * CHW) + kz * CHW + c;
        g_Ar[g] = ar; g_Ai[g] = ai;
    }
}

// --------- inverse z (irfft semantics: Re only, x2 for kz>0, 1/N scaling) ---------
__global__ void invz_k() {
    __shared__ float Dr[TTD][CHW], Di[TTD][CHW];
    __shared__ float cz[TTD][S3D], szt[TTD][S3D];
    int blk = blockIdx.x;            // b*4096 + n1*64 + n2
    int tid = threadIdx.x;
    size_t base = (size_t)blk * (TTD * CHW);
    for (int i = tid; i < TTD * CHW; i += 256) {
        Dr[i >> 6][i & 63] = g_Ar[base + i];
        Di[i >> 6][i & 63] = g_Ai[base + i];
    }
    for (int i = tid; i < TTD * S3D; i += 256) {
        int k = i / S3D, n = i % S3D;
        float s, c;
        sincospif((float)((2 * k * n) % 80) * (1.0f / 40.0f), &s, &c);
        float sc = (k == 0 ? 1.0f : 2.0f) * (1.0f / 163840.0f);  // 1/(64*64*40)
        cz[k][n] = c * sc; szt[k][n] = s * sc;
    }
    __syncthreads();
    int c = tid & 63, q = tid >> 6;
    float* op = g_s1 + (size_t)blk * (S3D * CHW);
    for (int n3 = q; n3 < S3D; n3 += 4) {
        float acc = 0;
#pragma unroll
        for (int k = 0; k < TTD; k++)
            acc += Dr[k][c] * cz[k][n3] - Di[k][c] * szt[k][n3];
        op[n3 * CHW + c] = acc;
    }
}

__device__ __forceinline__ float gelu_exact(float z) {
    return 0.5f * z * (1.0f + erff(z * 0.70710678118654752f));
}

// ------- fused per-layer pointwise: x = maybe_relu( W2*gelu(W1*s1+b1)+b2 + Ww*x+wb ) -------
__global__ void layer_k(const float* __restrict__ w1, const float* __restrict__ b1,
                        const float* __restrict__ w2, const float* __restrict__ b2,
                        const float* __restrict__ ww, const float* __restrict__ wb,
                        int do_relu) {
    extern __shared__ float sm[];
    float* w1T = sm;            // [i][o] pad 65
    float* w2T = sm + 4160;
    float* wwT = sm + 8320;
    float* sA  = sm + 12480;    // [p][c]
    float* sX  = sA + 4096;
    float* sH  = sX + 4096;
    int tid = threadIdx.y * 16 + threadIdx.x;
    int p0g = blockIdx.x * 64;
    for (int i = tid; i < 4096; i += 256) {
        int o = i >> 6, ic = i & 63;
        w1T[ic * 65 + o] = w1[i];
        w2T[ic * 65 + o] = w2[i];
        wwT[ic * 65 + o] = ww[i];
        sA[i] = g_s1[(size_t)p0g * 64 + i];
        sX[i] = g_x [(size_t)p0g * 64 + i];
    }
    __syncthreads();
    int o0 = threadIdx.x * 4, q0 = threadIdx.y * 4;
    float acc[4][4];
#pragma unroll
    for (int r = 0; r < 4; r++)
#pragma unroll
        for (int s = 0; s < 4; s++) acc[r][s] = 0.0f;
#pragma unroll 4
    for (int i = 0; i < 64; i++) {
        float a0 = sA[(q0 + 0) * 64 + i], a1 = sA[(q0 + 1) * 64 + i];
        float a2 = sA[(q0 + 2) * 64 + i], a3 = sA[(q0 + 3) * 64 + i];
        float wv0 = w1T[i * 65 + o0 + 0], wv1 = w1T[i * 65 + o0 + 1];
        float wv2 = w1T[i * 65 + o0 + 2], wv3 = w1T[i * 65 + o0 + 3];
        acc[0][0] += a0 * wv0; acc[0][1] += a0 * wv1; acc[0][2] += a0 * wv2; acc[0][3] += a0 * wv3;
        acc[1][0] += a1 * wv0; acc[1][1] += a1 * wv1; acc[1][2] += a1 * wv2; acc[1][3] += a1 * wv3;
        acc[2][0] += a2 * wv0; acc[2][1] += a2 * wv1; acc[2][2] += a2 * wv2; acc[2][3] += a2 * wv3;
        acc[3][0] += a3 * wv0; acc[3][1] += a3 * wv1; acc[3][2] += a3 * wv2; acc[3][3] += a3 * wv3;
    }
#pragma unroll
    for (int r = 0; r < 4; r++)
#pragma unroll
        for (int s = 0; s < 4; s++)
            sH[(q0 + r) * 64 + o0 + s] = gelu_exact(acc[r][s] + b1[o0 + s]);
    __syncthreads();
#pragma unroll
    for (int r = 0; r < 4; r++)
#pragma unroll
        for (int s = 0; s < 4; s++) acc[r][s] = 0.0f;
#pragma unroll 4
    for (int j = 0; j < 64; j++) {
        float h0 = sH[(q0 + 0) * 64 + j], h1 = sH[(q0 + 1) * 64 + j];
        float h2 = sH[(q0 + 2) * 64 + j], h3 = sH[(q0 + 3) * 64 + j];
        float wv0 = w2T[j * 65 + o0 + 0], wv1 = w2T[j * 65 + o0 + 1];
        float wv2 = w2T[j * 65 + o0 + 2], wv3 = w2T[j * 65 + o0 + 3];
        acc[0][0] += h0 * wv0; acc[0][1] += h0 * wv1; acc[0][2] += h0 * wv2; acc[0][3] += h0 * wv3;
        acc[1][0] += h1 * wv0; acc[1][1] += h1 * wv1; acc[1][2] += h1 * wv2; acc[1][3] += h1 * wv3;
        acc[2][0] += h2 * wv0; acc[2][1] += h2 * wv1; acc[2][2] += h2 * wv2; acc[2][3] += h2 * wv3;
        acc[3][0] += h3 * wv0; acc[3][1] += h3 * wv1; acc[3][2] += h3 * wv2; acc[3][3] += h3 * wv3;
    }
#pragma unroll 4
    for (int i = 0; i < 64; i++) {
        float x0 = sX[(q0 + 0) * 64 + i], x1 = sX[(q0 + 1) * 64 + i];
        float x2 = sX[(q0 + 2) * 64 + i], x3 = sX[(q0 + 3) * 64 + i];
        float wv0 = wwT[i * 65 + o0 + 0], wv1 = wwT[i * 65 + o0 + 1];
        float wv2 = wwT[i * 65 + o0 + 2], wv3 = wwT[i * 65 + o0 + 3];
        acc[0][0] += x0 * wv0; acc[0][1] += x0 * wv1; acc[0][2] += x0 * wv2; acc[0][3] += x0 * wv3;
        acc[1][0] += x1 * wv0; acc[1][1] += x1 * wv1; acc[1][2] += x1 * wv2; acc[1][3] += x1 * wv3;
        acc[2][0] += x2 * wv0; acc[2][1] += x2 * wv1; acc[2][2] += x2 * wv2; acc[2][3] += x2 * wv3;
        acc[3][0] += x3 * wv0; acc[3][1] += x3 * wv1; acc[3][2] += x3 * wv2; acc[3][3] += x3 * wv3;
    }
#pragma unroll
    for (int r = 0; r < 4; r++) {
#pragma unroll
        for (int s = 0; s < 4; s++) {
            float v = acc[r][s] + b2[o0 + s] + wb[o0 + s];
            if (do_relu) v = fmaxf(v, 0.0f);
            g_x[(size_t)(p0g + q0 + r) * 64 + o0 + s] = v;
        }
    }
}

// ---------------- final query MLP: 64 -> 256 (gelu) -> 1 ----------------
__global__ void qmlp_k(const float* __restrict__ w1, const float* __restrict__ b1,
                       const float* __restrict__ w2, const float* __restrict__ b2,
                       float* __restrict__ out) {
    extern __shared__ float sm[];
    float* sw1 = sm;              // [256][65]
    float* sx  = sm + 256 * 65;   // [64][64]
    float* sw2 = sx + 4096;       // [256]
    float* sb1 = sw2 + 256;       // [256]
    int tid = threadIdx.x;        // 256
    int p0g = blockIdx.x * 64;
    for (int i = tid; i < 256 * 64; i += 256) {
        int j = i >> 6, k = i & 63;
        sw1[j * 65 + k] = w1[i];
    }
    for (int i = tid; i < 4096; i += 256) sx[i] = g_x[(size_t)p0g * 64 + i];
    sw2[tid] = w2[tid];
    sb1[tid] = b1[tid];
    __syncthreads();
    int w = tid >> 5, lane = tid & 31;
    float qb = b2[0];
    for (int pl = 0; pl < 8; pl++) {
        int p = w * 8 + pl;
        float sum = 0.0f;
#pragma unroll
        for (int m = 0; m < 8; m++) {
            int j = lane + 32 * m;
            float acc = sb1[j];
            const float* wr = &sw1[j * 65];
#pragma unroll 8
            for (int k = 0; k < 64; k++) acc += wr[k] * sx[p * 64 + k];
            sum += sw2[j] * gelu_exact(acc);
        }
#pragma unroll
        for (int off = 16; off; off >>= 1) sum += __shfl_down_sync(0xffffffffu, sum, off);
        if (lane == 0) out[p0g + p] = sum + qb;
    }
}

// ---------------- host launcher ----------------
extern "C" void kernel_launch(void* const* d_in, const int* in_sizes, int n_in,
                              void* d_out, int out_size) {
    const float* x_in   = (const float*)d_in[0];
    const float* p_w    = (const float*)d_in[1];
    const float* p_b    = (const float*)d_in[2];
    const float* W_LC   = (const float*)d_in[3];
    const float* W_LR   = (const float*)d_in[4];
    const float* mlp_w1 = (const float*)d_in[5];
    const float* mlp_b1 = (const float*)d_in[6];
    const float* mlp_w2 = (const float*)d_in[7];
    const float* mlp_b2 = (const float*)d_in[8];
    const float* w_w    = (const float*)d_in[9];
    const float* w_b    = (const float*)d_in[10];
    const float* q_w1   = (const float*)d_in[11];
    const float* q_b1   = (const float*)d_in[12];
    const float* q_w2   = (const float*)d_in[13];
    const float* q_b2   = (const float*)d_in[14];
    float* out = (float*)d_out;

    const int LAYER_SMEM = 24768 * 4;                       // 99072 B
    const int QMLP_SMEM  = (256 * 65 + 4096 + 512) * 4;     // 84992 B
    cudaFuncSetAttribute(layer_k, cudaFuncAttributeMaxDynamicSharedMemorySize, LAYER_SMEM);
    cudaFuncSetAttribute(qmlp_k,  cudaFuncAttributeMaxDynamicSharedMemorySize, QMLP_SMEM);

    // weight transposes to mode-major
    transpose_k<<<dim3(3, 128, NLAY),  dim3(32, 8)>>>(W_LC, 4096, 96,  0);
    transpose_k<<<dim3(31, 128, NLAY), dim3(32, 8)>>>(W_LR, 4096, 968, 1);

    lift_k<<<(NPTS * CHW) / 256, 256>>>(x_in, p_w, p_b);

    for (int l = 0; l < NLAY; l++) {
        fwdz_k<<<BB * S1D * S2D, 256>>>();
        fwdy_k<<<BB * S2D * TTD, 256>>>();
        fwdx_k<<<BB * MMD * TTD, 256>>>();
        mix_k <<<MMD * MMD * TTD, 128>>>(l);
        invy_k<<<BB * MMD * TTD, 256>>>();
        invx_k<<<BB * S1D * TTD, 256>>>();
        invz_k<<<BB * S1D * S2D, 256>>>();
        layer_k<<<NPTS / 64, dim3(16, 16), LAYER_SMEM>>>(
            mlp_w1 + l * 4096, mlp_b1 + l * 64,
            mlp_w2 + l * 4096, mlp_b2 + l * 64,
            w_w + l * 4096,    w_b + l * 64,
            (l < NLAY - 1) ? 1 : 0);
    }

    qmlp_k<<<NPTS / 64, 256, QMLP_SMEM>>>(q_w1, q_b1, q_w2, q_b2, out);
}

// round 2
// speedup vs baseline: 1.5062x; 1.5062x over previous
#include <cuda_runtime.h>
#include <math.h>

#define BB 2
#define S1D 64
#define S2D 64
#define S3D 40
#define CHW 64
#define MMD 23
#define TTD 8
#define NPTS (BB*S1D*S2D*S3D)   // 327680
#define NLAY 4

// ---------------- device scratch (static, allocation-free, 16B aligned) ----------------
__device__ __align__(16) float g_x [NPTS*CHW];
__device__ __align__(16) float g_s1[NPTS*CHW];
__device__ __align__(16) float g_Ar[BB*S1D*S2D*TTD*CHW];
__device__ __align__(16) float g_Ai[BB*S1D*S2D*TTD*CHW];
__device__ __align__(16) float g_Br[BB*MMD*S2D*TTD*CHW];
__device__ __align__(16) float g_Bi[BB*MMD*S2D*TTD*CHW];
__device__ __align__(16) float g_Xr[BB*MMD*MMD*TTD*CHW];
__device__ __align__(16) float g_Xi[BB*MMD*MMD*TTD*CHW];
__device__ __align__(16) float g_Yr[BB*MMD*MMD*TTD*CHW];
__device__ __align__(16) float g_Yi[BB*MMD*MMD*TTD*CHW];
__device__ __align__(16) float g_wlc[NLAY*12*TTD*CHW*CHW];     // [l][a*8+kz][i*64+o]
__device__ __align__(16) float g_wlr[NLAY*11*11*TTD*CHW*CHW];  // [l][(p*11+q)*8+kz][i*64+o]

// twiddle tables
__device__ __align__(16) float t_fz[S3D][16];      // [n][2k]=cos, [2k+1]=sin
__device__ __align__(16) float t_iz[S3D][16];      // scaled inverse-z
__device__ __align__(16) float t_fy[S1D][48];      // [n][ky]=cos (pad 24), [n][24+ky]=sin
__device__ __align__(16) float t_iy[MMD][128];     // [ky][n]=cos, [ky][64+n]=sin

__device__ __forceinline__ float4 f4fma(float4 a, float s, float4 acc) {
    acc.x = fmaf(a.x, s, acc.x); acc.y = fmaf(a.y, s, acc.y);
    acc.z = fmaf(a.z, s, acc.z); acc.w = fmaf(a.w, s, acc.w);
    return acc;
}
__device__ __forceinline__ float4 f4zero() { return make_float4(0.f, 0.f, 0.f, 0.f); }

// ---------------- twiddle init (once per launch, tiny) ----------------
__global__ void init_tw_k() {
    int tid = threadIdx.x;   // 256
    for (int i = tid; i < TTD * S3D; i += 256) {
        int k = i / S3D, n = i % S3D;
        float s, c;
        sincospif((float)((2 * k * n) % 80) * (1.0f / 40.0f), &s, &c);
        t_fz[n][2 * k] = c; t_fz[n][2 * k + 1] = s;
        float sc = (k == 0 ? 1.0f : 2.0f) * (1.0f / 163840.0f);
        t_iz[n][2 * k] = c * sc; t_iz[n][2 * k + 1] = s * sc;
    }
    for (int i = tid; i < S1D * 24; i += 256) {
        int n = i / 24, ky = i % 24;
        float c = 0.f, s = 0.f;
        if (ky < MMD) {
            int t = ((ky - 11) * n) & 63;
            sincospif((float)t * (1.0f / 32.0f), &s, &c);
        }
        t_fy[n][ky] = c; t_fy[n][24 + ky] = s;
        if (ky < MMD) { t_iy[ky][n] = c; t_iy[ky][64 + n] = s; }
    }
}

// ---------------- weight transpose: [l][io][m] -> [l][m][io] ----------------
__global__ void transpose_k(const float* __restrict__ src, int rows, int cols, int which) {
    __shared__ float tile[32][33];
    float* dst = which ? g_wlr : g_wlc;
    int l = blockIdx.z;
    const float* s = src + (size_t)l * rows * cols;
    float* d = dst + (size_t)l * rows * cols;
    int c0 = blockIdx.x * 32, r0 = blockIdx.y * 32;
    int tx = threadIdx.x;
    for (int dy = threadIdx.y; dy < 32; dy += 8) {
        int r = r0 + dy, c = c0 + tx;
        if (r < rows && c < cols) tile[dy][tx] = s[(size_t)r * cols + c];
    }
    __syncthreads();
    for (int dy = threadIdx.y; dy < 32; dy += 8) {
        int c = c0 + dy, r = r0 + tx;
        if (r < rows && c < cols) d[(size_t)c * rows + r] = tile[tx][dy];
    }
}

// ---------------- lift: x(.,10) + grid(3) -> 64 channels ----------------
__global__ void lift_k(const float* __restrict__ xin, const float* __restrict__ pw,
                       const float* __restrict__ pb) {
    int e = blockIdx.x * 256 + threadIdx.x;
    if (e >= NPTS * CHW) return;
    int c = e & 63;
    int p = e >> 6;
    int n3 = p % S3D;
    int r = p / S3D;
    int n2 = r & 63; r >>= 6;
    int n1 = r & 63;
    const float* xp = xin + (size_t)p * 10;
    const float* w = pw + c * 13;
    float acc = pb[c];
#pragma unroll
    for (int i = 0; i < 10; i++) acc += w[i] * xp[i];
    acc += w[10] * (n1 * (1.0f / 63.0f));
    acc += w[11] * (n2 * (1.0f / 63.0f));
    acc += w[12] * (n3 * (1.0f / 39.0f));
    g_x[e] = acc;
}

// ---------------- forward z-DFT: real 40 -> complex 8 (direct LDG, no staging) ----------------
__global__ void fwdz_k() {
    __shared__ __align__(16) float tw[S3D][16];
    int tid = threadIdx.x;  // 256, 8 columns per block (one per warp)
    for (int i = tid; i < S3D * 16; i += 256) tw[i >> 4][i & 15] = t_fz[i >> 4][i & 15];
    __syncthreads();
    int col = blockIdx.x * 8 + (tid >> 5);
    int lane = tid & 31;
    int cg = lane & 15, kzg = lane >> 4;
    const float4* xp = (const float4*)g_x + (size_t)col * 640 + cg;
    float4 ar[4], ai[4];
#pragma unroll
    for (int j = 0; j < 4; j++) { ar[j] = f4zero(); ai[j] = f4zero(); }
#pragma unroll 8
    for (int n = 0; n < S3D; n++) {
        float4 v = xp[n * 16];
        float4 t0 = *(const float4*)&tw[n][kzg * 8];
        float4 t1 = *(const float4*)&tw[n][kzg * 8 + 4];
        ar[0] = f4fma(v,  t0.x, ar[0]); ai[0] = f4fma(v, -t0.y, ai[0]);
        ar[1] = f4fma(v,  t0.z, ar[1]); ai[1] = f4fma(v, -t0.w, ai[1]);
        ar[2] = f4fma(v,  t1.x, ar[2]); ai[2] = f4fma(v, -t1.y, ai[2]);
        ar[3] = f4fma(v,  t1.z, ar[3]); ai[3] = f4fma(v, -t1.w, ai[3]);
    }
    float4* Ar4 = (float4*)g_Ar;
    float4* Ai4 = (float4*)g_Ai;
    size_t base = (size_t)col * 128 + kzg * 64 + cg;
#pragma unroll
    for (int j = 0; j < 4; j++) {
        Ar4[base + j * 16] = ar[j];
        Ai4[base + j * 16] = ai[j];
    }
}

// ---------------- forward y-DFT: n1 (64) -> ky (23) ----------------
__global__ void fwdy_k() {
    __shared__ __align__(16) float Sr[S1D][CHW], Si[S1D][CHW];
    __shared__ __align__(16) float twf[S1D][48];
    int tid = threadIdx.x;  // 96
    int blk = blockIdx.x;
    int kz = blk & 7, rest = blk >> 3;
    int n2 = rest & 63, b = rest >> 6;
    const float4* Ar4 = (const float4*)g_Ar;
    const float4* Ai4 = (const float4*)g_Ai;
    for (int i = tid; i < 1024; i += 96) {
        int n1 = i >> 4, c4 = i & 15;
        size_t g4 = ((((size_t)b * S1D + n1) * S2D + n2) * TTD + kz) * 16 + c4;
        *(float4*)&Sr[n1][c4 * 4] = Ar4[g4];
        *(float4*)&Si[n1][c4 * 4] = Ai4[g4];
    }
    for (int i = tid; i < 768; i += 96) ((float4*)twf)[i] = ((const float4*)t_fy)[i];
    __syncthreads();
    int cg = tid & 15, kg = tid >> 4;   // kg 0..5
    float4 ar[4], ai[4];
#pragma unroll
    for (int j = 0; j < 4; j++) { ar[j] = f4zero(); ai[j] = f4zero(); }
#pragma unroll 4
    for (int n = 0; n < S1D; n++) {
        float4 xr = *(const float4*)&Sr[n][cg * 4];
        float4 xi = *(const float4*)&Si[n][cg * 4];
        float4 tc = *(const float4*)&twf[n][kg * 4];
        float4 ts = *(const float4*)&twf[n][24 + kg * 4];
        ar[0]=f4fma(xr,tc.x,ar[0]); ar[0]=f4fma(xi,ts.x,ar[0]); ai[0]=f4fma(xi,tc.x,ai[0]); ai[0]=f4fma(xr,-ts.x,ai[0]);
        ar[1]=f4fma(xr,tc.y,ar[1]); ar[1]=f4fma(xi,ts.y,ar[1]); ai[1]=f4fma(xi,tc.y,ai[1]); ai[1]=f4fma(xr,-ts.y,ai[1]);
        ar[2]=f4fma(xr,tc.z,ar[2]); ar[2]=f4fma(xi,ts.z,ar[2]); ai[2]=f4fma(xi,tc.z,ai[2]); ai[2]=f4fma(xr,-ts.z,ai[2]);
        ar[3]=f4fma(xr,tc.w,ar[3]); ar[3]=f4fma(xi,ts.w,ar[3]); ai[3]=f4fma(xi,tc.w,ai[3]); ai[3]=f4fma(xr,-ts.w,ai[3]);
    }
    float4* Br4 = (float4*)g_Br;
    float4* Bi4 = (float4*)g_Bi;
#pragma unroll
    for (int j = 0; j < 4; j++) {
        int ky = kg * 4 + j;
        if (ky < MMD) {
            size_t g4 = ((((size_t)b * MMD + ky) * S2D + n2) * TTD + kz) * 16 + cg;
            Br4[g4] = ar[j]; Bi4[g4] = ai[j];
        }
    }
}

// ---------------- forward x-DFT: n2 (64) -> kx (23) ----------------
__global__ void fwdx_k() {
    __shared__ __align__(16) float Sr[S2D][CHW], Si[S2D][CHW];
    __shared__ __align__(16) float twf[S2D][48];
    int tid = threadIdx.x;  // 96
    int blk = blockIdx.x;
    int kz = blk & 7, rest = blk >> 3;
    int ky = rest % MMD, b = rest / MMD;
    const float4* Br4 = (const float4*)g_Br;
    const float4* Bi4 = (const float4*)g_Bi;
    for (int i = tid; i < 1024; i += 96) {
        int n2 = i >> 4, c4 = i & 15;
        size_t g4 = ((((size_t)b * MMD + ky) * S2D + n2) * TTD + kz) * 16 + c4;
        *(float4*)&Sr[n2][c4 * 4] = Br4[g4];
        *(float4*)&Si[n2][c4 * 4] = Bi4[g4];
    }
    for (int i = tid; i < 768; i += 96) ((float4*)twf)[i] = ((const float4*)t_fy)[i];
    __syncthreads();
    int cg = tid & 15, kg = tid >> 4;
    float4 ar[4], ai[4];
#pragma unroll
    for (int j = 0; j < 4; j++) { ar[j] = f4zero(); ai[j] = f4zero(); }
#pragma unroll 4
    for (int n = 0; n < S2D; n++) {
        float4 xr = *(const float4*)&Sr[n][cg * 4];
        float4 xi = *(const float4*)&Si[n][cg * 4];
        float4 tc = *(const float4*)&twf[n][kg * 4];
        float4 ts = *(const float4*)&twf[n][24 + kg * 4];
        ar[0]=f4fma(xr,tc.x,ar[0]); ar[0]=f4fma(xi,ts.x,ar[0]); ai[0]=f4fma(xi,tc.x,ai[0]); ai[0]=f4fma(xr,-ts.x,ai[0]);
        ar[1]=f4fma(xr,tc.y,ar[1]); ar[1]=f4fma(xi,ts.y,ar[1]); ai[1]=f4fma(xi,tc.y,ai[1]); ai[1]=f4fma(xr,-ts.y,ai[1]);
        ar[2]=f4fma(xr,tc.z,ar[2]); ar[2]=f4fma(xi,ts.z,ar[2]); ai[2]=f4fma(xi,tc.z,ai[2]); ai[2]=f4fma(xr,-ts.z,ai[2]);
        ar[3]=f4fma(xr,tc.w,ar[3]); ar[3]=f4fma(xi,ts.w,ar[3]); ai[3]=f4fma(xi,tc.w,ai[3]); ai[3]=f4fma(xr,-ts.w,ai[3]);
    }
    float4* Xr4 = (float4*)g_Xr;
    float4* Xi4 = (float4*)g_Xi;
#pragma unroll
    for (int j = 0; j < 4; j++) {
        int kx = kg * 4 + j;
        if (kx < MMD) {
            size_t g4 = ((((size_t)b * MMD + ky) * MMD + kx) * TTD + kz) * 16 + cg;
            Xr4[g4] = ar[j]; Xi4[g4] = ai[j];
        }
    }
}

// --------- mode -> (sel, a, b) mapping replicating _spectral_weights ---------
__device__ __forceinline__ void map_mode(int y, int x, int& sel, int& ia, int& ib) {
    int yy, s;
    if (x >= 11) { yy = y; s = x - 11; }
    else         { yy = 22 - y; s = 11 - x; }
    int r, t;
    if (yy < 12) {
        if (s == 0) { sel = 0; ia = 11 - yy; ib = 0; return; }
        r = s - 1; t = 11 - yy;
    } else { r = yy - 12; t = s; }
    if (t == 0) { sel = 0; ia = r + 1; ib = 0; }
    else        { sel = 1; ia = r;     ib = t - 1; }
}

// ---------------- per-mode 64x64 channel mix ----------------
__global__ void mix_k(int l) {
    __shared__ __align__(16) float xs[BB][2][CHW];
    __shared__ __align__(16) float red[8][256];
    int m = blockIdx.x;
    int kz = m % TTD, x = (m / TTD) % MMD, y = m / (TTD * MMD);
    int sel, ia, ib;
    map_mode(y, x, sel, ia, ib);
    const float* wp;
    if (sel == 0) wp = g_wlc + (((size_t)l * 12 + ia) * TTD + kz) * (CHW * CHW);
    else          wp = g_wlr + (((size_t)l * 121 + ia * 11 + ib) * TTD + kz) * (CHW * CHW);
    int tid = threadIdx.x;   // 128
    if (tid < 128) {
        int b = tid >> 6, c = tid & 63;
        size_t g = ((((size_t)b * MMD + y) * MMD + x) * TTD + kz) * CHW + c;
        xs[b][0][c] = g_Xr[g];
        xs[b][1][c] = g_Xi[g];
    }
    __syncthreads();
    int ks = tid >> 4, og = tid & 15;
    float4 a00 = f4zero(), a01 = f4zero(), a10 = f4zero(), a11 = f4zero();
    const float4* wp4 = (const float4*)wp;
#pragma unroll
    for (int it = 0; it < 8; it++) {
        int i = ks * 8 + it;
        float4 w = wp4[i * 16 + og];
        a00 = f4fma(w, xs[0][0][i], a00);
        a01 = f4fma(w, xs[0][1][i], a01);
        a10 = f4fma(w, xs[1][0][i], a10);
        a11 = f4fma(w, xs[1][1][i], a11);
    }
    *(float4*)&red[ks][  0 + og * 4] = a00;
    *(float4*)&red[ks][ 64 + og * 4] = a01;
    *(float4*)&red[ks][128 + og * 4] = a10;
    *(float4*)&red[ks][192 + og * 4] = a11;
    __syncthreads();
    for (int v = tid; v < 256; v += 128) {
        float s = 0.f;
#pragma unroll
        for (int k = 0; k < 8; k++) s += red[k][v];
        int b = v >> 7, ri = (v >> 6) & 1, o = v & 63;
        size_t g = ((((size_t)b * MMD + y) * MMD + x) * TTD + kz) * CHW + o;
        if (ri) g_Yi[g] = s; else g_Yr[g] = s;
    }
}

// ---------------- inverse y: ky (23) -> n1 (64) ----------------
__global__ void invy_k() {
    __shared__ __align__(16) float Sr[MMD][CHW], Si[MMD][CHW];
    __shared__ __align__(16) float twi[MMD][128];
    int tid = threadIdx.x;  // 256
    int blk = blockIdx.x;
    int kz = blk & 7, rest = blk >> 3;
    int kx = rest % MMD, b = rest / MMD;
    const float4* Yr4 = (const float4*)g_Yr;
    const float4* Yi4 = (const float4*)g_Yi;
    for (int i = tid; i < MMD * 16; i += 256) {
        int ky = i >> 4, c4 = i & 15;
        size_t g4 = ((((size_t)b * MMD + ky) * MMD + kx) * TTD + kz) * 16 + c4;
        *(float4*)&Sr[ky][c4 * 4] = Yr4[g4];
        *(float4*)&Si[ky][c4 * 4] = Yi4[g4];
    }
    for (int i = tid; i < 736; i += 256) ((float4*)twi)[i] = ((const float4*)t_iy)[i];
    __syncthreads();
    int cg = tid & 15, ng = tid >> 4;
    int n0 = ng * 4;
    float4 ar[4], ai[4];
#pragma unroll
    for (int j = 0; j < 4; j++) { ar[j] = f4zero(); ai[j] = f4zero(); }
#pragma unroll
    for (int ky = 0; ky < MMD; ky++) {
        float4 xr = *(const float4*)&Sr[ky][cg * 4];
        float4 xi = *(const float4*)&Si[ky][cg * 4];
        float4 tc = *(const float4*)&twi[ky][n0];
        float4 ts = *(const float4*)&twi[ky][64 + n0];
        ar[0]=f4fma(xr,tc.x,ar[0]); ar[0]=f4fma(xi,-ts.x,ar[0]); ai[0]=f4fma(xr,ts.x,ai[0]); ai[0]=f4fma(xi,tc.x,ai[0]);
        ar[1]=f4fma(xr,tc.y,ar[1]); ar[1]=f4fma(xi,-ts.y,ar[1]); ai[1]=f4fma(xr,ts.y,ai[1]); ai[1]=f4fma(xi,tc.y,ai[1]);
        ar[2]=f4fma(xr,tc.z,ar[2]); ar[2]=f4fma(xi,-ts.z,ar[2]); ai[2]=f4fma(xr,ts.z,ai[2]); ai[2]=f4fma(xi,tc.z,ai[2]);
        ar[3]=f4fma(xr,tc.w,ar[3]); ar[3]=f4fma(xi,-ts.w,ar[3]); ai[3]=f4fma(xr,ts.w,ai[3]); ai[3]=f4fma(xi,tc.w,ai[3]);
    }
    float4* Br4 = (float4*)g_Br;
    float4* Bi4 = (float4*)g_Bi;
#pragma unroll
    for (int j = 0; j < 4; j++) {
        int n1 = n0 + j;
        size_t g4 = ((((size_t)b * S1D + n1) * MMD + kx) * TTD + kz) * 16 + cg;
        Br4[g4] = ar[j]; Bi4[g4] = ai[j];
    }
}

// ---------------- inverse x: kx (23) -> n2 (64) ----------------
__global__ void invx_k() {
    __shared__ __align__(16) float Sr[MMD][CHW], Si[MMD][CHW];
    __shared__ __align__(16) float twi[MMD][128];
    int tid = threadIdx.x;  // 256
    int blk = blockIdx.x;
    int kz = blk & 7, rest = blk >> 3;
    int n1 = rest & 63, b = rest >> 6;
    const float4* Br4 = (const float4*)g_Br;
    const float4* Bi4 = (const float4*)g_Bi;
    for (int i = tid; i < MMD * 16; i += 256) {
        int kx = i >> 4, c4 = i & 15;
        size_t g4 = ((((size_t)b * S1D + n1) * MMD + kx) * TTD + kz) * 16 + c4;
        *(float4*)&Sr[kx][c4 * 4] = Br4[g4];
        *(float4*)&Si[kx][c4 * 4] = Bi4[g4];
    }
    for (int i = tid; i < 736; i += 256) ((float4*)twi)[i] = ((const float4*)t_iy)[i];
    __syncthreads();
    int cg = tid & 15, ng = tid >> 4;
    int n0 = ng * 4;
    float4 ar[4], ai[4];
#pragma unroll
    for (int j = 0; j < 4; j++) { ar[j] = f4zero(); ai[j] = f4zero(); }
#pragma unroll
    for (int kx = 0; kx < MMD; kx++) {
        float4 xr = *(const float4*)&Sr[kx][cg * 4];
        float4 xi = *(const float4*)&Si[kx][cg * 4];
        float4 tc = *(const float4*)&twi[kx][n0];
        float4 ts = *(const float4*)&twi[kx][64 + n0];
        ar[0]=f4fma(xr,tc.x,ar[0]); ar[0]=f4fma(xi,-ts.x,ar[0]); ai[0]=f4fma(xr,ts.x,ai[0]); ai[0]=f4fma(xi,tc.x,ai[0]);
        ar[1]=f4fma(xr,tc.y,ar[1]); ar[1]=f4fma(xi,-ts.y,ar[1]); ai[1]=f4fma(xr,ts.y,ai[1]); ai[1]=f4fma(xi,tc.y,ai[1]);
        ar[2]=f4fma(xr,tc.z,ar[2]); ar[2]=f4fma(xi,-ts.z,ar[2]); ai[2]=f4fma(xr,ts.z,ai[2]); ai[2]=f4fma(xi,tc.z,ai[2]);
        ar[3]=f4fma(xr,tc.w,ar[3]); ar[3]=f4fma(xi,-ts.w,ar[3]); ai[3]=f4fma(xr,ts.w,ai[3]); ai[3]=f4fma(xi,tc.w,ai[3]);
    }
    float4* Ar4 = (float4*)g_Ar;
    float4* Ai4 = (float4*)g_Ai;
#pragma unroll
    for (int j = 0; j < 4; j++) {
        int n2 = n0 + j;
        size_t g4 = ((((size_t)b * S1D + n1) * S2D + n2) * TTD + kz) * 16 + cg;
        Ar4[g4] = ar[j]; Ai4[g4] = ai[j];
    }
}

// --------- inverse z: complex 8 -> real 40 (registers, direct LDG/STG) ---------
__global__ void invz_k() {
    __shared__ __align__(16) float tw[S3D][16];
    int tid = threadIdx.x;  // 256, 16 columns per block
    for (int i = tid; i < S3D * 16; i += 256) tw[i >> 4][i & 15] = t_iz[i >> 4][i & 15];
    __syncthreads();
    int col = blockIdx.x * 16 + (tid >> 4);
    int cg = tid & 15;
    const float4* Ar4 = (const float4*)g_Ar;
    const float4* Ai4 = (const float4*)g_Ai;
    float4 dr[TTD], di[TTD];
    size_t base = (size_t)col * 128 + cg;
#pragma unroll
    for (int k = 0; k < TTD; k++) {
        dr[k] = Ar4[base + k * 16];
        di[k] = Ai4[base + k * 16];
    }
    float4* s14 = (float4*)g_s1;
    size_t obase = (size_t)col * 640 + cg;
#pragma unroll 4
    for (int n3 = 0; n3 < S3D; n3++) {
        float4 t0 = *(const float4*)&tw[n3][0];
        float4 t1 = *(const float4*)&tw[n3][4];
        float4 t2 = *(const float4*)&tw[n3][8];
        float4 t3 = *(const float4*)&tw[n3][12];
        float4 acc = f4zero();
        acc = f4fma(dr[0],  t0.x, acc); acc = f4fma(di[0], -t0.y, acc);
        acc = f4fma(dr[1],  t0.z, acc); acc = f4fma(di[1], -t0.w, acc);
        acc = f4fma(dr[2],  t1.x, acc); acc = f4fma(di[2], -t1.y, acc);
        acc = f4fma(dr[3],  t1.z, acc); acc = f4fma(di[3], -t1.w, acc);
        acc = f4fma(dr[4],  t2.x, acc); acc = f4fma(di[4], -t2.y, acc);
        acc = f4fma(dr[5],  t2.z, acc); acc = f4fma(di[5], -t2.w, acc);
        acc = f4fma(dr[6],  t3.x, acc); acc = f4fma(di[6], -t3.y, acc);
        acc = f4fma(dr[7],  t3.z, acc); acc = f4fma(di[7], -t3.w, acc);
        s14[obase + n3 * 16] = acc;
    }
}

__device__ __forceinline__ float gelu_exact(float z) {
    return 0.5f * z * (1.0f + erff(z * 0.70710678118654752f));
}

// ------- fused per-layer pointwise: x = maybe_relu( W2*gelu(W1*s1+b1)+b2 + Ww*x+wb ) -------
__global__ void layer_k(const float* __restrict__ w1, const float* __restrict__ b1,
                        const float* __restrict__ w2, const float* __restrict__ b2,
                        const float* __restrict__ ww, const float* __restrict__ wb,
                        int do_relu) {
    extern __shared__ float sm[];
    float* w1T = sm;             // [i][65]
    float* w2T = sm + 4160;
    float* wwT = sm + 8320;
    float* sA  = sm + 12480;     // [p][64]
    float* sX  = sA + 4096;
    float* sH  = sX + 4096;
    int tx = threadIdx.x, ty = threadIdx.y;
    int tid = ty * 16 + tx;
    int p0g = blockIdx.x * 64;
    for (int i = tid; i < 4096; i += 256) {
        int o = i >> 6, ic = i & 63;
        w1T[ic * 65 + o] = w1[i];
        w2T[ic * 65 + o] = w2[i];
        wwT[ic * 65 + o] = ww[i];
    }
    {
        const float4* s14 = (const float4*)g_s1 + (size_t)p0g * 16;
        const float4* x4  = (const float4*)g_x  + (size_t)p0g * 16;
        float4* sA4 = (float4*)sA;
        float4* sX4 = (float4*)sX;
        for (int i = tid; i < 1024; i += 256) { sA4[i] = s14[i]; sX4[i] = x4[i]; }
    }
    __syncthreads();
    int o0 = tx * 4, q0 = ty * 4;
    float acc[4][4];
#pragma unroll
    for (int r = 0; r < 4; r++)
#pragma unroll
        for (int s = 0; s < 4; s++) acc[r][s] = 0.0f;

#pragma unroll 4
    for (int ic = 0; ic < 64; ic += 4) {
        float a[4][4];
#pragma unroll
        for (int r = 0; r < 4; r++) {
            float4 t = *(const float4*)&sA[(q0 + r) * 64 + ic];
            a[r][0] = t.x; a[r][1] = t.y; a[r][2] = t.z; a[r][3] = t.w;
        }
#pragma unroll
        for (int kk = 0; kk < 4; kk++) {
            float wv0 = w1T[(ic + kk) * 65 + o0 + 0];
            float wv1 = w1T[(ic + kk) * 65 + o0 + 1];
            float wv2 = w1T[(ic + kk) * 65 + o0 + 2];
            float wv3 = w1T[(ic + kk) * 65 + o0 + 3];
#pragma unroll
            for (int r = 0; r < 4; r++) {
                acc[r][0] = fmaf(a[r][kk], wv0, acc[r][0]);
                acc[r][1] = fmaf(a[r][kk], wv1, acc[r][1]);
                acc[r][2] = fmaf(a[r][kk], wv2, acc[r][2]);
                acc[r][3] = fmaf(a[r][kk], wv3, acc[r][3]);
            }
        }
    }
#pragma unroll
    for (int r = 0; r < 4; r++) {
        float4 h;
        h.x = gelu_exact(acc[r][0] + b1[o0 + 0]);
        h.y = gelu_exact(acc[r][1] + b1[o0 + 1]);
        h.z = gelu_exact(acc[r][2] + b1[o0 + 2]);
        h.w = gelu_exact(acc[r][3] + b1[o0 + 3]);
        *(float4*)&sH[(q0 + r) * 64 + o0] = h;
    }
    __syncthreads();
#pragma unroll
    for (int r = 0; r < 4; r++)
#pragma unroll
        for (int s = 0; s < 4; s++) acc[r][s] = 0.0f;

#pragma unroll 4
    for (int ic = 0; ic < 64; ic += 4) {
        float a[4][4];
#pragma unroll
        for (int r = 0; r < 4; r++) {
            float4 t = *(const float4*)&sH[(q0 + r) * 64 + ic];
            a[r][0] = t.x; a[r][1] = t.y; a[r][2] = t.z; a[r][3] = t.w;
        }
#pragma unroll
        for (int kk = 0; kk < 4; kk++) {
            float wv0 = w2T[(ic + kk) * 65 + o0 + 0];
            float wv1 = w2T[(ic + kk) * 65 + o0 + 1];
            float wv2 = w2T[(ic + kk) * 65 + o0 + 2];
            float wv3 = w2T[(ic + kk) * 65 + o0 + 3];
#pragma unroll
            for (int r = 0; r < 4; r++) {
                acc[r][0] = fmaf(a[r][kk], wv0, acc[r][0]);
                acc[r][1] = fmaf(a[r][kk], wv1, acc[r][1]);
                acc[r][2] = fmaf(a[r][kk], wv2, acc[r][2]);
                acc[r][3] = fmaf(a[r][kk], wv3, acc[r][3]);
            }
        }
    }
#pragma unroll 4
    for (int ic = 0; ic < 64; ic += 4) {
        float a[4][4];
#pragma unroll
        for (int r = 0; r < 4; r++) {
            float4 t = *(const float4*)&sX[(q0 + r) * 64 + ic];
            a[r][0] = t.x; a[r][1] = t.y; a[r][2] = t.z; a[r][3] = t.w;
        }
#pragma unroll
        for (int kk = 0; kk < 4; kk++) {
            float wv0 = wwT[(ic + kk) * 65 + o0 + 0];
            float wv1 = wwT[(ic + kk) * 65 + o0 + 1];
            float wv2 = wwT[(ic + kk) * 65 + o0 + 2];
            float wv3 = wwT[(ic + kk) * 65 + o0 + 3];
#pragma unroll
            for (int r = 0; r < 4; r++) {
                acc[r][0] = fmaf(a[r][kk], wv0, acc[r][0]);
                acc[r][1] = fmaf(a[r][kk], wv1, acc[r][1]);
                acc[r][2] = fmaf(a[r][kk], wv2, acc[r][2]);
                acc[r][3] = fmaf(a[r][kk], wv3, acc[r][3]);
            }
        }
    }
    float bb0 = b2[o0 + 0] + wb[o0 + 0];
    float bb1 = b2[o0 + 1] + wb[o0 + 1];
    float bb2 = b2[o0 + 2] + wb[o0 + 2];
    float bb3 = b2[o0 + 3] + wb[o0 + 3];
#pragma unroll
    for (int r = 0; r < 4; r++) {
        float4 v;
        v.x = acc[r][0] + bb0; v.y = acc[r][1] + bb1;
        v.z = acc[r][2] + bb2; v.w = acc[r][3] + bb3;
        if (do_relu) {
            v.x = fmaxf(v.x, 0.f); v.y = fmaxf(v.y, 0.f);
            v.z = fmaxf(v.z, 0.f); v.w = fmaxf(v.w, 0.f);
        }
        *(float4*)&g_x[(size_t)(p0g + q0 + r) * 64 + o0] = v;
    }
}

// ---------------- final query MLP: 64 -> 256 (gelu) -> 1 ----------------
__global__ void qmlp_k(const float* __restrict__ w1, const float* __restrict__ b1,
                       const float* __restrict__ w2, const float* __restrict__ b2,
                       float* __restrict__ out) {
    extern __shared__ float sm[];
    float* w1T = sm;              // [k 64][j 257-pad]
    float* sx  = sm + 64 * 257;   // [p][64]
    int tx = threadIdx.x, ty = threadIdx.y;
    int tid = ty * 16 + tx;
    int p0g = blockIdx.x * 64;
    for (int i = tid; i < 256 * 64; i += 256) {
        int j = i >> 6, k = i & 63;
        w1T[k * 257 + j] = w1[i];
    }
    {
        const float4* x4 = (const float4*)g_x + (size_t)p0g * 16;
        float4* sx4 = (float4*)sx;
        for (int i = tid; i < 1024; i += 256) sx4[i] = x4[i];
    }
    __syncthreads();
    int p0 = ty * 4;
    float po[4] = {0.f, 0.f, 0.f, 0.f};
#pragma unroll
    for (int jb = 0; jb < 4; jb++) {
        int j0 = jb * 64 + tx * 4;
        float acc[4][4];
#pragma unroll
        for (int r = 0; r < 4; r++)
#pragma unroll
            for (int s = 0; s < 4; s++) acc[r][s] = 0.f;
#pragma unroll 4
        for (int kc = 0; kc < 64; kc += 4) {
            float a[4][4];
#pragma unroll
            for (int r = 0; r < 4; r++) {
                float4 t = *(const float4*)&sx[(p0 + r) * 64 + kc];
                a[r][0] = t.x; a[r][1] = t.y; a[r][2] = t.z; a[r][3] = t.w;
            }
#pragma unroll
            for (int kk = 0; kk < 4; kk++) {
                float wv0 = w1T[(kc + kk) * 257 + j0 + 0];
                float wv1 = w1T[(kc + kk) * 257 + j0 + 1];
                float wv2 = w1T[(kc + kk) * 257 + j0 + 2];
                float wv3 = w1T[(kc + kk) * 257 + j0 + 3];
#pragma unroll
                for (int r = 0; r < 4; r++) {
                    acc[r][0] = fmaf(a[r][kk], wv0, acc[r][0]);
                    acc[r][1] = fmaf(a[r][kk], wv1, acc[r][1]);
                    acc[r][2] = fmaf(a[r][kk], wv2, acc[r][2]);
                    acc[r][3] = fmaf(a[r][kk], wv3, acc[r][3]);
                }
            }
        }
#pragma unroll
        for (int s = 0; s < 4; s++) {
            float bv = b1[j0 + s];
            float wv = w2[j0 + s];
#pragma unroll
            for (int r = 0; r < 4; r++)
                po[r] = fmaf(wv, gelu_exact(acc[r][s] + bv), po[r]);
        }
    }
#pragma unroll
    for (int off = 8; off; off >>= 1) {
#pragma unroll
        for (int r = 0; r < 4; r++)
            po[r] += __shfl_down_sync(0xffffffffu, po[r], off);
    }
    if (tx == 0) {
        float qb = b2[0];
#pragma unroll
        for (int r = 0; r < 4; r++) out[p0g + p0 + r] = po[r] + qb;
    }
}

// ---------------- host launcher ----------------
extern "C" void kernel_launch(void* const* d_in, const int* in_sizes, int n_in,
                              void* d_out, int out_size) {
    const float* x_in   = (const float*)d_in[0];
    const float* p_w    = (const float*)d_in[1];
    const float* p_b    = (const float*)d_in[2];
    const float* W_LC   = (const float*)d_in[3];
    const float* W_LR   = (const float*)d_in[4];
    const float* mlp_w1 = (const float*)d_in[5];
    const float* mlp_b1 = (const float*)d_in[6];
    const float* mlp_w2 = (const float*)d_in[7];
    const float* mlp_b2 = (const float*)d_in[8];
    const float* w_w    = (const float*)d_in[9];
    const float* w_b    = (const float*)d_in[10];
    const float* q_w1   = (const float*)d_in[11];
    const float* q_b1   = (const float*)d_in[12];
    const float* q_w2   = (const float*)d_in[13];
    const float* q_b2   = (const float*)d_in[14];
    float* out = (float*)d_out;

    const int LAYER_SMEM = 24768 * 4;                   // 99072 B
    const int QMLP_SMEM  = (64 * 257 + 4096) * 4;       // 82176 B
    cudaFuncSetAttribute(layer_k, cudaFuncAttributeMaxDynamicSharedMemorySize, LAYER_SMEM);
    cudaFuncSetAttribute(qmlp_k,  cudaFuncAttributeMaxDynamicSharedMemorySize, QMLP_SMEM);

    init_tw_k<<<1, 256>>>();
    transpose_k<<<dim3(3, 128, NLAY),  dim3(32, 8)>>>(W_LC, 4096, 96,  0);
    transpose_k<<<dim3(31, 128, NLAY), dim3(32, 8)>>>(W_LR, 4096, 968, 1);

    lift_k<<<(NPTS * CHW) / 256, 256>>>(x_in, p_w, p_b);

    for (int l = 0; l < NLAY; l++) {
        fwdz_k<<<BB * S1D * S2D / 8, 256>>>();
        fwdy_k<<<BB * S2D * TTD, 96>>>();
        fwdx_k<<<BB * MMD * TTD, 96>>>();
        mix_k <<<MMD * MMD * TTD, 128>>>(l);
        invy_k<<<BB * MMD * TTD, 256>>>();
        invx_k<<<BB * S1D * TTD, 256>>>();
        invz_k<<<BB * S1D * S2D / 16, 256>>>();
        layer_k<<<NPTS / 64, dim3(16, 16), LAYER_SMEM>>>(
            mlp_w1 + l * 4096, mlp_b1 + l * 64,
            mlp_w2 + l * 4096, mlp_b2 + l * 64,
            w_w + l * 4096,    w_b + l * 64,
            (l < NLAY - 1) ? 1 : 0);
    }

    qmlp_k<<<NPTS / 64, dim3(16, 16), QMLP_SMEM>>>(q_w1, q_b1, q_w2, q_b2, out);
}

// round 4
// speedup vs baseline: 2.0681x; 1.3730x over previous
#include <cuda_runtime.h>
#include <math.h>

#define BB 2
#define S1D 64
#define S2D 64
#define S3D 40
#define CHW 64
#define MMD 23
#define TTD 8
#define NPTS (BB*S1D*S2D*S3D)   // 327680
#define NLAY 4

// ---------------- device scratch (static, allocation-free, 16B aligned) ----------------
__device__ __align__(16) float g_x [NPTS*CHW];
__device__ __align__(16) float g_Ar[BB*S1D*S2D*TTD*CHW];
__device__ __align__(16) float g_Ai[BB*S1D*S2D*TTD*CHW];
__device__ __align__(16) float g_Br[BB*MMD*S2D*TTD*CHW];
__device__ __align__(16) float g_Bi[BB*MMD*S2D*TTD*CHW];
__device__ __align__(16) float g_Xr[BB*MMD*MMD*TTD*CHW];
__device__ __align__(16) float g_Xi[BB*MMD*MMD*TTD*CHW];
__device__ __align__(16) float g_Yr[BB*MMD*MMD*TTD*CHW];
__device__ __align__(16) float g_Yi[BB*MMD*MMD*TTD*CHW];
__device__ __align__(16) float g_wlc[NLAY*12*TTD*CHW*CHW];     // [l][a*8+kz][i*64+o]
__device__ __align__(16) float g_wlr[NLAY*11*11*TTD*CHW*CHW];  // [l][(p*11+q)*8+kz][i*64+o]

// twiddle tables
__device__ __align__(16) float t_fz[S3D][16];      // [n][2k]=cos, [2k+1]=sin
__device__ __align__(16) float t_iz[S3D][16];      // scaled inverse-z
__device__ __align__(16) float t_fy[S1D][48];      // [n][ky]=cos (pad 24), [n][24+ky]=sin
__device__ __align__(16) float t_iy[MMD][128];     // [ky][n]=cos, [ky][64+n]=sin

__device__ __forceinline__ float4 f4fma(float4 a, float s, float4 acc) {
    acc.x = fmaf(a.x, s, acc.x); acc.y = fmaf(a.y, s, acc.y);
    acc.z = fmaf(a.z, s, acc.z); acc.w = fmaf(a.w, s, acc.w);
    return acc;
}
__device__ __forceinline__ float4 f4zero() { return make_float4(0.f, 0.f, 0.f, 0.f); }

__device__ __forceinline__ float gelu_exact(float z) {
    return 0.5f * z * (1.0f + erff(z * 0.70710678118654752f));
}

// ---------------- twiddle init ----------------
__global__ void init_tw_k() {
    int tid = threadIdx.x;   // 256
    for (int i = tid; i < TTD * S3D; i += 256) {
        int k = i / S3D, n = i % S3D;
        float s, c;
        sincospif((float)((2 * k * n) % 80) * (1.0f / 40.0f), &s, &c);
        t_fz[n][2 * k] = c; t_fz[n][2 * k + 1] = s;
        float sc = (k == 0 ? 1.0f : 2.0f) * (1.0f / 163840.0f);
        t_iz[n][2 * k] = c * sc; t_iz[n][2 * k + 1] = s * sc;
    }
    for (int i = tid; i < S1D * 24; i += 256) {
        int n = i / 24, ky = i % 24;
        float c = 0.f, s = 0.f;
        if (ky < MMD) {
            int t = ((ky - 11) * n) & 63;
            sincospif((float)t * (1.0f / 32.0f), &s, &c);
        }
        t_fy[n][ky] = c; t_fy[n][24 + ky] = s;
        if (ky < MMD) { t_iy[ky][n] = c; t_iy[ky][64 + n] = s; }
    }
}

// ---------------- weight transpose: [l][io][m] -> [l][m][io] ----------------
__global__ void transpose_k(const float* __restrict__ src, int rows, int cols, int which) {
    __shared__ float tile[32][33];
    float* dst = which ? g_wlr : g_wlc;
    int l = blockIdx.z;
    const float* s = src + (size_t)l * rows * cols;
    float* d = dst + (size_t)l * rows * cols;
    int c0 = blockIdx.x * 32, r0 = blockIdx.y * 32;
    int tx = threadIdx.x;
    for (int dy = threadIdx.y; dy < 32; dy += 8) {
        int r = r0 + dy, c = c0 + tx;
        if (r < rows && c < cols) tile[dy][tx] = s[(size_t)r * cols + c];
    }
    __syncthreads();
    for (int dy = threadIdx.y; dy < 32; dy += 8) {
        int c = c0 + dy, r = r0 + tx;
        if (r < rows && c < cols) d[(size_t)c * rows + r] = tile[tx][dy];
    }
}

// ---------------- lift: smem-staged, float4 everywhere ----------------
__global__ void lift_k(const float* __restrict__ xin, const float* __restrict__ pw,
                       const float* __restrict__ pb) {
    __shared__ float wT[13 * 64];   // [i][c]
    __shared__ float xs[64 * 10];
    int tid = threadIdx.x;          // 256
    // transpose pw [c][13] -> wT [i][c]
    for (int j = tid; j < 832; j += 256) {
        int c = j / 13, i = j % 13;
        wT[i * 64 + c] = pw[j];
    }
    int p0g = blockIdx.x * 64;
    for (int j = tid; j < 640; j += 256) xs[j] = xin[(size_t)p0g * 10 + j];
    __syncthreads();

    int c0 = (tid & 15) * 4;
    float4 pb4 = *(const float4*)&pb[c0];
    float4 w10 = *(const float4*)&wT[10 * 64 + c0];
    float4 w11 = *(const float4*)&wT[11 * 64 + c0];
    float4 w12 = *(const float4*)&wT[12 * 64 + c0];
#pragma unroll
    for (int pass = 0; pass < 4; pass++) {
        int pl = pass * 16 + (tid >> 4);
        int p = p0g + pl;
        int n3 = p % S3D;
        int r = p / S3D;
        int n2 = r & 63; r >>= 6;
        int n1 = r & 63;
        float4 acc = pb4;
        acc = f4fma(w10, n1 * (1.0f / 63.0f), acc);
        acc = f4fma(w11, n2 * (1.0f / 63.0f), acc);
        acc = f4fma(w12, n3 * (1.0f / 39.0f), acc);
        const float* xp = &xs[pl * 10];
#pragma unroll
        for (int i = 0; i < 10; i++) {
            float4 wv = *(const float4*)&wT[i * 64 + c0];
            acc = f4fma(wv, xp[i], acc);
        }
        *(float4*)&g_x[(size_t)p * 64 + c0] = acc;
    }
}

// ---------------- forward z-DFT: real 40 -> complex 8 ----------------
__global__ void fwdz_k() {
    __shared__ __align__(16) float tw[S3D][16];
    int tid = threadIdx.x;  // 256, 8 columns per block (one per warp)
    for (int i = tid; i < S3D * 16; i += 256) tw[i >> 4][i & 15] = t_fz[i >> 4][i & 15];
    __syncthreads();
    int col = blockIdx.x * 8 + (tid >> 5);
    int lane = tid & 31;
    int cg = lane & 15, kzg = lane >> 4;
    const float4* xp = (const float4*)g_x + (size_t)col * 640 + cg;
    float4 ar[4], ai[4];
#pragma unroll
    for (int j = 0; j < 4; j++) { ar[j] = f4zero(); ai[j] = f4zero(); }
#pragma unroll 8
    for (int n = 0; n < S3D; n++) {
        float4 v = xp[n * 16];
        float4 t0 = *(const float4*)&tw[n][kzg * 8];
        float4 t1 = *(const float4*)&tw[n][kzg * 8 + 4];
        ar[0] = f4fma(v,  t0.x, ar[0]); ai[0] = f4fma(v, -t0.y, ai[0]);
        ar[1] = f4fma(v,  t0.z, ar[1]); ai[1] = f4fma(v, -t0.w, ai[1]);
        ar[2] = f4fma(v,  t1.x, ar[2]); ai[2] = f4fma(v, -t1.y, ai[2]);
        ar[3] = f4fma(v,  t1.z, ar[3]); ai[3] = f4fma(v, -t1.w, ai[3]);
    }
    float4* Ar4 = (float4*)g_Ar;
    float4* Ai4 = (float4*)g_Ai;
    size_t base = (size_t)col * 128 + kzg * 64 + cg;
#pragma unroll
    for (int j = 0; j < 4; j++) {
        Ar4[base + j * 16] = ar[j];
        Ai4[base + j * 16] = ai[j];
    }
}

// ---------------- forward y-DFT: n1 (64) -> ky (23) ----------------
__global__ void fwdy_k() {
    __shared__ __align__(16) float Sr[S1D][CHW], Si[S1D][CHW];
    __shared__ __align__(16) float twf[S1D][48];
    int tid = threadIdx.x;  // 96
    int blk = blockIdx.x;
    int kz = blk & 7, rest = blk >> 3;
    int n2 = rest & 63, b = rest >> 6;
    const float4* Ar4 = (const float4*)g_Ar;
    const float4* Ai4 = (const float4*)g_Ai;
    for (int i = tid; i < 1024; i += 96) {
        int n1 = i >> 4, c4 = i & 15;
        size_t g4 = ((((size_t)b * S1D + n1) * S2D + n2) * TTD + kz) * 16 + c4;
        *(float4*)&Sr[n1][c4 * 4] = Ar4[g4];
        *(float4*)&Si[n1][c4 * 4] = Ai4[g4];
    }
    for (int i = tid; i < 768; i += 96) ((float4*)twf)[i] = ((const float4*)t_fy)[i];
    __syncthreads();
    int cg = tid & 15, kg = tid >> 4;   // kg 0..5
    float4 ar[4], ai[4];
#pragma unroll
    for (int j = 0; j < 4; j++) { ar[j] = f4zero(); ai[j] = f4zero(); }
#pragma unroll 4
    for (int n = 0; n < S1D; n++) {
        float4 xr = *(const float4*)&Sr[n][cg * 4];
        float4 xi = *(const float4*)&Si[n][cg * 4];
        float4 tc = *(const float4*)&twf[n][kg * 4];
        float4 ts = *(const float4*)&twf[n][24 + kg * 4];
        ar[0]=f4fma(xr,tc.x,ar[0]); ar[0]=f4fma(xi,ts.x,ar[0]); ai[0]=f4fma(xi,tc.x,ai[0]); ai[0]=f4fma(xr,-ts.x,ai[0]);
        ar[1]=f4fma(xr,tc.y,ar[1]); ar[1]=f4fma(xi,ts.y,ar[1]); ai[1]=f4fma(xi,tc.y,ai[1]); ai[1]=f4fma(xr,-ts.y,ai[1]);
        ar[2]=f4fma(xr,tc.z,ar[2]); ar[2]=f4fma(xi,ts.z,ar[2]); ai[2]=f4fma(xi,tc.z,ai[2]); ai[2]=f4fma(xr,-ts.z,ai[2]);
        ar[3]=f4fma(xr,tc.w,ar[3]); ar[3]=f4fma(xi,ts.w,ar[3]); ai[3]=f4fma(xi,tc.w,ai[3]); ai[3]=f4fma(xr,-ts.w,ai[3]);
    }
    float4* Br4 = (float4*)g_Br;
    float4* Bi4 = (float4*)g_Bi;
#pragma unroll
    for (int j = 0; j < 4; j++) {
        int ky = kg * 4 + j;
        if (ky < MMD) {
            size_t g4 = ((((size_t)b * MMD + ky) * S2D + n2) * TTD + kz) * 16 + cg;
            Br4[g4] = ar[j]; Bi4[g4] = ai[j];
        }
    }
}

// ---------------- forward x-DFT: n2 (64) -> kx (23) ----------------
__global__ void fwdx_k() {
    __shared__ __align__(16) float Sr[S2D][CHW], Si[S2D][CHW];
    __shared__ __align__(16) float twf[S2D][48];
    int tid = threadIdx.x;  // 96
    int blk = blockIdx.x;
    int kz = blk & 7, rest = blk >> 3;
    int ky = rest % MMD, b = rest / MMD;
    const float4* Br4 = (const float4*)g_Br;
    const float4* Bi4 = (const float4*)g_Bi;
    for (int i = tid; i < 1024; i += 96) {
        int n2 = i >> 4, c4 = i & 15;
        size_t g4 = ((((size_t)b * MMD + ky) * S2D + n2) * TTD + kz) * 16 + c4;
        *(float4*)&Sr[n2][c4 * 4] = Br4[g4];
        *(float4*)&Si[n2][c4 * 4] = Bi4[g4];
    }
    for (int i = tid; i < 768; i += 96) ((float4*)twf)[i] = ((const float4*)t_fy)[i];
    __syncthreads();
    int cg = tid & 15, kg = tid >> 4;
    float4 ar[4], ai[4];
#pragma unroll
    for (int j = 0; j < 4; j++) { ar[j] = f4zero(); ai[j] = f4zero(); }
#pragma unroll 4
    for (int n = 0; n < S2D; n++) {
        float4 xr = *(const float4*)&Sr[n][cg * 4];
        float4 xi = *(const float4*)&Si[n][cg * 4];
        float4 tc = *(const float4*)&twf[n][kg * 4];
        float4 ts = *(const float4*)&twf[n][24 + kg * 4];
        ar[0]=f4fma(xr,tc.x,ar[0]); ar[0]=f4fma(xi,ts.x,ar[0]); ai[0]=f4fma(xi,tc.x,ai[0]); ai[0]=f4fma(xr,-ts.x,ai[0]);
        ar[1]=f4fma(xr,tc.y,ar[1]); ar[1]=f4fma(xi,ts.y,ar[1]); ai[1]=f4fma(xi,tc.y,ai[1]); ai[1]=f4fma(xr,-ts.y,ai[1]);
        ar[2]=f4fma(xr,tc.z,ar[2]); ar[2]=f4fma(xi,ts.z,ar[2]); ai[2]=f4fma(xi,tc.z,ai[2]); ai[2]=f4fma(xr,-ts.z,ai[2]);
        ar[3]=f4fma(xr,tc.w,ar[3]); ar[3]=f4fma(xi,ts.w,ar[3]); ai[3]=f4fma(xi,tc.w,ai[3]); ai[3]=f4fma(xr,-ts.w,ai[3]);
    }
    float4* Xr4 = (float4*)g_Xr;
    float4* Xi4 = (float4*)g_Xi;
#pragma unroll
    for (int j = 0; j < 4; j++) {
        int kx = kg * 4 + j;
        if (kx < MMD) {
            size_t g4 = ((((size_t)b * MMD + ky) * MMD + kx) * TTD + kz) * 16 + cg;
            Xr4[g4] = ar[j]; Xi4[g4] = ai[j];
        }
    }
}

// --------- mode -> (sel, a, b) mapping replicating _spectral_weights ---------
__device__ __forceinline__ void map_mode(int y, int x, int& sel, int& ia, int& ib) {
    int yy, s;
    if (x >= 11) { yy = y; s = x - 11; }
    else         { yy = 22 - y; s = 11 - x; }
    int r, t;
    if (yy < 12) {
        if (s == 0) { sel = 0; ia = 11 - yy; ib = 0; return; }
        r = s - 1; t = 11 - yy;
    } else { r = yy - 12; t = s; }
    if (t == 0) { sel = 0; ia = r + 1; ib = 0; }
    else        { sel = 1; ia = r;     ib = t - 1; }
}

// ---------------- per-mode 64x64 channel mix ----------------
__global__ void mix_k(int l) {
    __shared__ __align__(16) float xs[BB][2][CHW];
    __shared__ __align__(16) float red[8][256];
    int m = blockIdx.x;
    int kz = m % TTD, x = (m / TTD) % MMD, y = m / (TTD * MMD);
    int sel, ia, ib;
    map_mode(y, x, sel, ia, ib);
    const float* wp;
    if (sel == 0) wp = g_wlc + (((size_t)l * 12 + ia) * TTD + kz) * (CHW * CHW);
    else          wp = g_wlr + (((size_t)l * 121 + ia * 11 + ib) * TTD + kz) * (CHW * CHW);
    int tid = threadIdx.x;   // 128
    if (tid < 128) {
        int b = tid >> 6, c = tid & 63;
        size_t g = ((((size_t)b * MMD + y) * MMD + x) * TTD + kz) * CHW + c;
        xs[b][0][c] = g_Xr[g];
        xs[b][1][c] = g_Xi[g];
    }
    __syncthreads();
    int ks = tid >> 4, og = tid & 15;
    float4 a00 = f4zero(), a01 = f4zero(), a10 = f4zero(), a11 = f4zero();
    const float4* wp4 = (const float4*)wp;
#pragma unroll
    for (int it = 0; it < 8; it++) {
        int i = ks * 8 + it;
        float4 w = wp4[i * 16 + og];
        a00 = f4fma(w, xs[0][0][i], a00);
        a01 = f4fma(w, xs[0][1][i], a01);
        a10 = f4fma(w, xs[1][0][i], a10);
        a11 = f4fma(w, xs[1][1][i], a11);
    }
    *(float4*)&red[ks][  0 + og * 4] = a00;
    *(float4*)&red[ks][ 64 + og * 4] = a01;
    *(float4*)&red[ks][128 + og * 4] = a10;
    *(float4*)&red[ks][192 + og * 4] = a11;
    __syncthreads();
    for (int v = tid; v < 256; v += 128) {
        float s = 0.f;
#pragma unroll
        for (int k = 0; k < 8; k++) s += red[k][v];
        int b = v >> 7, ri = (v >> 6) & 1, o = v & 63;
        size_t g = ((((size_t)b * MMD + y) * MMD + x) * TTD + kz) * CHW + o;
        if (ri) g_Yi[g] = s; else g_Yr[g] = s;
    }
}

// ---------------- inverse y: ky (23) -> n1 (64) ----------------
__global__ void invy_k() {
    __shared__ __align__(16) float Sr[MMD][CHW], Si[MMD][CHW];
    __shared__ __align__(16) float twi[MMD][128];
    int tid = threadIdx.x;  // 256
    int blk = blockIdx.x;
    int kz = blk & 7, rest = blk >> 3;
    int kx = rest % MMD, b = rest / MMD;
    const float4* Yr4 = (const float4*)g_Yr;
    const float4* Yi4 = (const float4*)g_Yi;
    for (int i = tid; i < MMD * 16; i += 256) {
        int ky = i >> 4, c4 = i & 15;
        size_t g4 = ((((size_t)b * MMD + ky) * MMD + kx) * TTD + kz) * 16 + c4;
        *(float4*)&Sr[ky][c4 * 4] = Yr4[g4];
        *(float4*)&Si[ky][c4 * 4] = Yi4[g4];
    }
    for (int i = tid; i < 736; i += 256) ((float4*)twi)[i] = ((const float4*)t_iy)[i];
    __syncthreads();
    int cg = tid & 15, ng = tid >> 4;
    int n0 = ng * 4;
    float4 ar[4], ai[4];
#pragma unroll
    for (int j = 0; j < 4; j++) { ar[j] = f4zero(); ai[j] = f4zero(); }
#pragma unroll
    for (int ky = 0; ky < MMD; ky++) {
        float4 xr = *(const float4*)&Sr[ky][cg * 4];
        float4 xi = *(const float4*)&Si[ky][cg * 4];
        float4 tc = *(const float4*)&twi[ky][n0];
        float4 ts = *(const float4*)&twi[ky][64 + n0];
        ar[0]=f4fma(xr,tc.x,ar[0]); ar[0]=f4fma(xi,-ts.x,ar[0]); ai[0]=f4fma(xr,ts.x,ai[0]); ai[0]=f4fma(xi,tc.x,ai[0]);
        ar[1]=f4fma(xr,tc.y,ar[1]); ar[1]=f4fma(xi,-ts.y,ar[1]); ai[1]=f4fma(xr,ts.y,ai[1]); ai[1]=f4fma(xi,tc.y,ai[1]);
        ar[2]=f4fma(xr,tc.z,ar[2]); ar[2]=f4fma(xi,-ts.z,ar[2]); ai[2]=f4fma(xr,ts.z,ai[2]); ai[2]=f4fma(xi,tc.z,ai[2]);
        ar[3]=f4fma(xr,tc.w,ar[3]); ar[3]=f4fma(xi,-ts.w,ar[3]); ai[3]=f4fma(xr,ts.w,ai[3]); ai[3]=f4fma(xi,tc.w,ai[3]);
    }
    float4* Br4 = (float4*)g_Br;
    float4* Bi4 = (float4*)g_Bi;
#pragma unroll
    for (int j = 0; j < 4; j++) {
        int n1 = n0 + j;
        size_t g4 = ((((size_t)b * S1D + n1) * MMD + kx) * TTD + kz) * 16 + cg;
        Br4[g4] = ar[j]; Bi4[g4] = ai[j];
    }
}

// ---------------- inverse x: kx (23) -> n2 (64) ----------------
__global__ void invx_k() {
    __shared__ __align__(16) float Sr[MMD][CHW], Si[MMD][CHW];
    __shared__ __align__(16) float twi[MMD][128];
    int tid = threadIdx.x;  // 256
    int blk = blockIdx.x;
    int kz = blk & 7, rest = blk >> 3;
    int n1 = rest & 63, b = rest >> 6;
    const float4* Br4 = (const float4*)g_Br;
    const float4* Bi4 = (const float4*)g_Bi;
    for (int i = tid; i < MMD * 16; i += 256) {
        int kx = i >> 4, c4 = i & 15;
        size_t g4 = ((((size_t)b * S1D + n1) * MMD + kx) * TTD + kz) * 16 + c4;
        *(float4*)&Sr[kx][c4 * 4] = Br4[g4];
        *(float4*)&Si[kx][c4 * 4] = Bi4[g4];
    }
    for (int i = tid; i < 736; i += 256) ((float4*)twi)[i] = ((const float4*)t_iy)[i];
    __syncthreads();
    int cg = tid & 15, ng = tid >> 4;
    int n0 = ng * 4;
    float4 ar[4], ai[4];
#pragma unroll
    for (int j = 0; j < 4; j++) { ar[j] = f4zero(); ai[j] = f4zero(); }
#pragma unroll
    for (int kx = 0; kx < MMD; kx++) {
        float4 xr = *(const float4*)&Sr[kx][cg * 4];
        float4 xi = *(const float4*)&Si[kx][cg * 4];
        float4 tc = *(const float4*)&twi[kx][n0];
        float4 ts = *(const float4*)&twi[kx][64 + n0];
        ar[0]=f4fma(xr,tc.x,ar[0]); ar[0]=f4fma(xi,-ts.x,ar[0]); ai[0]=f4fma(xr,ts.x,ai[0]); ai[0]=f4fma(xi,tc.x,ai[0]);
        ar[1]=f4fma(xr,tc.y,ar[1]); ar[1]=f4fma(xi,-ts.y,ar[1]); ai[1]=f4fma(xr,ts.y,ai[1]); ai[1]=f4fma(xi,tc.y,ai[1]);
        ar[2]=f4fma(xr,tc.z,ar[2]); ar[2]=f4fma(xi,-ts.z,ar[2]); ai[2]=f4fma(xr,ts.z,ai[2]); ai[2]=f4fma(xi,tc.z,ai[2]);
        ar[3]=f4fma(xr,tc.w,ar[3]); ar[3]=f4fma(xi,-ts.w,ar[3]); ai[3]=f4fma(xr,ts.w,ai[3]); ai[3]=f4fma(xi,tc.w,ai[3]);
    }
    float4* Ar4 = (float4*)g_Ar;
    float4* Ai4 = (float4*)g_Ai;
#pragma unroll
    for (int j = 0; j < 4; j++) {
        int n2 = n0 + j;
        size_t g4 = ((((size_t)b * S1D + n1) * S2D + n2) * TTD + kz) * 16 + cg;
        Ar4[g4] = ar[j]; Ai4[g4] = ai[j];
    }
}

// ===== fused invz + MLP + skip, persistent, weights loaded once per block =====
// smem floats (dense stride-64 weight tiles for 16B-aligned float4 loads):
// w1T[4096] w2T[4096] wwT[4096] sX[5120] sA[5120] sH[5120(>=D 2048)] tw[640]
#define FUSE_SMEMF (4096*3 + 5120*3 + 640)   // 28288 floats = 113152 B
__global__ void __launch_bounds__(256, 2)
fuse_k(const float* __restrict__ w1, const float* __restrict__ b1,
       const float* __restrict__ w2, const float* __restrict__ b2,
       const float* __restrict__ ww, const float* __restrict__ wb,
       int do_relu) {
    extern __shared__ float sm[];
    float* w1T = sm;
    float* w2T = sm + 4096;
    float* wwT = sm + 8192;
    float* sX  = sm + 12288;
    float* sA  = sm + 17408;
    float* sH  = sm + 22528;   // also D region: Dr f4[0..255], Di f4[256..511]
    float* tw  = sm + 27648;
    int tx = threadIdx.x & 15, ty = threadIdx.x >> 4;
    int tid = threadIdx.x;

    for (int i = tid; i < 4096; i += 256) {
        int o = i >> 6, ic = i & 63;
        w1T[ic * 64 + o] = w1[i];
        w2T[ic * 64 + o] = w2[i];
        wwT[ic * 64 + o] = ww[i];
    }
    for (int i = tid; i < 640; i += 256) tw[i] = ((const float*)t_iz)[i];

    int o0 = tx * 4, q0 = ty * 5;
    float b1v[4], bbv[4];
#pragma unroll
    for (int s = 0; s < 4; s++) {
        b1v[s] = b1[o0 + s];
        bbv[s] = b2[o0 + s] + wb[o0 + s];
    }
    __syncthreads();

    const float4* Ar4 = (const float4*)g_Ar;
    const float4* Ai4 = (const float4*)g_Ai;
    float4* dD = (float4*)sH;

    for (int pair = blockIdx.x; pair < 4096; pair += gridDim.x) {
        size_t pbase = (size_t)pair * 80;
        size_t colg = (size_t)pair * 2;
        // load D (both columns) + sX
        dD[tid]       = Ar4[colg * 128 + tid];
        dD[256 + tid] = Ai4[colg * 128 + tid];
        {
            const float4* gx4 = (const float4*)g_x + pbase * 16;
            float4* sX4 = (float4*)sX;
#pragma unroll
            for (int i = 0; i < 5; i++) sX4[tid + i * 256] = gx4[tid + i * 256];
        }
        __syncthreads();

        // ---- invz: sA[80][64] ----
        {
            int cg = tid & 15, rg = tid >> 4;
            int ccprev = -1;
            float4 dr[8], di[8];
#pragma unroll
            for (int r = 0; r < 5; r++) {
                int row = rg * 5 + r;
                int cc = (row >= 40) ? 1 : 0;
                int n3 = row - cc * 40;
                if (cc != ccprev) {
#pragma unroll
                    for (int k = 0; k < 8; k++) {
                        dr[k] = dD[cc * 128 + k * 16 + cg];
                        di[k] = dD[256 + cc * 128 + k * 16 + cg];
                    }
                    ccprev = cc;
                }
                float4 t0 = *(const float4*)&tw[n3 * 16 + 0];
                float4 t1 = *(const float4*)&tw[n3 * 16 + 4];
                float4 t2 = *(const float4*)&tw[n3 * 16 + 8];
                float4 t3 = *(const float4*)&tw[n3 * 16 + 12];
                float4 acc = f4zero();
                acc = f4fma(dr[0],  t0.x, acc); acc = f4fma(di[0], -t0.y, acc);
                acc = f4fma(dr[1],  t0.z, acc); acc = f4fma(di[1], -t0.w, acc);
                acc = f4fma(dr[2],  t1.x, acc); acc = f4fma(di[2], -t1.y, acc);
                acc = f4fma(dr[3],  t1.z, acc); acc = f4fma(di[3], -t1.w, acc);
                acc = f4fma(dr[4],  t2.x, acc); acc = f4fma(di[4], -t2.y, acc);
                acc = f4fma(dr[5],  t2.z, acc); acc = f4fma(di[5], -t2.w, acc);
                acc = f4fma(dr[6],  t3.x, acc); acc = f4fma(di[6], -t3.y, acc);
                acc = f4fma(dr[7],  t3.z, acc); acc = f4fma(di[7], -t3.w, acc);
                *(float4*)&sA[row * 64 + cg * 4] = acc;
            }
        }
        __syncthreads();

        float acc[5][4];
        // ---- GEMM1: H = gelu(W1 * s1 + b1) ----
#pragma unroll
        for (int r = 0; r < 5; r++)
#pragma unroll
            for (int s = 0; s < 4; s++) acc[r][s] = 0.f;
#pragma unroll 4
        for (int ic = 0; ic < 64; ic += 4) {
            float a[5][4];
#pragma unroll
            for (int r = 0; r < 5; r++) {
                float4 t = *(const float4*)&sA[(q0 + r) * 64 + ic];
                a[r][0] = t.x; a[r][1] = t.y; a[r][2] = t.z; a[r][3] = t.w;
            }
#pragma unroll
            for (int kk = 0; kk < 4; kk++) {
                float4 w = *(const float4*)&w1T[(ic + kk) * 64 + o0];
#pragma unroll
                for (int r = 0; r < 5; r++) {
                    acc[r][0] = fmaf(a[r][kk], w.x, acc[r][0]);
                    acc[r][1] = fmaf(a[r][kk], w.y, acc[r][1]);
                    acc[r][2] = fmaf(a[r][kk], w.z, acc[r][2]);
                    acc[r][3] = fmaf(a[r][kk], w.w, acc[r][3]);
                }
            }
        }
        __syncthreads();   // D region done being read; safe to overwrite as sH
#pragma unroll
        for (int r = 0; r < 5; r++) {
            float4 h;
            h.x = gelu_exact(acc[r][0] + b1v[0]);
            h.y = gelu_exact(acc[r][1] + b1v[1]);
            h.z = gelu_exact(acc[r][2] + b1v[2]);
            h.w = gelu_exact(acc[r][3] + b1v[3]);
            *(float4*)&sH[(q0 + r) * 64 + o0] = h;
        }
        __syncthreads();

        // ---- GEMM2 (W2*H) + GEMM3 (Ww*X) ----
#pragma unroll
        for (int r = 0; r < 5; r++)
#pragma unroll
            for (int s = 0; s < 4; s++) acc[r][s] = 0.f;
#pragma unroll 4
        for (int ic = 0; ic < 64; ic += 4) {
            float a[5][4];
#pragma unroll
            for (int r = 0; r < 5; r++) {
                float4 t = *(const float4*)&sH[(q0 + r) * 64 + ic];
                a[r][0] = t.x; a[r][1] = t.y; a[r][2] = t.z; a[r][3] = t.w;
            }
#pragma unroll
            for (int kk = 0; kk < 4; kk++) {
                float4 w = *(const float4*)&w2T[(ic + kk) * 64 + o0];
#pragma unroll
                for (int r = 0; r < 5; r++) {
                    acc[r][0] = fmaf(a[r][kk], w.x, acc[r][0]);
                    acc[r][1] = fmaf(a[r][kk], w.y, acc[r][1]);
                    acc[r][2] = fmaf(a[r][kk], w.z, acc[r][2]);
                    acc[r][3] = fmaf(a[r][kk], w.w, acc[r][3]);
                }
            }
        }
#pragma unroll 4
        for (int ic = 0; ic < 64; ic += 4) {
            float a[5][4];
#pragma unroll
            for (int r = 0; r < 5; r++) {
                float4 t = *(const float4*)&sX[(q0 + r) * 64 + ic];
                a[r][0] = t.x; a[r][1] = t.y; a[r][2] = t.z; a[r][3] = t.w;
            }
#pragma unroll
            for (int kk = 0; kk < 4; kk++) {
                float4 w = *(const float4*)&wwT[(ic + kk) * 64 + o0];
#pragma unroll
                for (int r = 0; r < 5; r++) {
                    acc[r][0] = fmaf(a[r][kk], w.x, acc[r][0]);
                    acc[r][1] = fmaf(a[r][kk], w.y, acc[r][1]);
                    acc[r][2] = fmaf(a[r][kk], w.z, acc[r][2]);
                    acc[r][3] = fmaf(a[r][kk], w.w, acc[r][3]);
                }
            }
        }
#pragma unroll
        for (int r = 0; r < 5; r++) {
            float4 v;
            v.x = acc[r][0] + bbv[0]; v.y = acc[r][1] + bbv[1];
            v.z = acc[r][2] + bbv[2]; v.w = acc[r][3] + bbv[3];
            if (do_relu) {
                v.x = fmaxf(v.x, 0.f); v.y = fmaxf(v.y, 0.f);
                v.z = fmaxf(v.z, 0.f); v.w = fmaxf(v.w, 0.f);
            }
            *(float4*)&g_x[(pbase + q0 + r) * 64 + o0] = v;
        }
        __syncthreads();   // protect sX/sH/sA before next pair
    }
}

// ---------------- final query MLP: 64 -> 256 (gelu) -> 1, persistent ----------------
// w1T stride 260 (multiple of 4 -> aligned float4 reads)
__global__ void __launch_bounds__(256, 2)
qmlp_k(const float* __restrict__ w1, const float* __restrict__ b1,
       const float* __restrict__ w2, const float* __restrict__ b2,
       float* __restrict__ out) {
    extern __shared__ float sm[];
    float* w1T = sm;              // [k 64][j 260-pad]
    float* sx  = sm + 64 * 260;   // [p][64]
    int tx = threadIdx.x & 15, ty = threadIdx.x >> 4;
    int tid = threadIdx.x;
    for (int i = tid; i < 256 * 64; i += 256) {
        int j = i >> 6, k = i & 63;
        w1T[k * 260 + j] = w1[i];
    }
    __syncthreads();
    float qb = b2[0];
    int p0 = ty * 4;

    for (int tile = blockIdx.x; tile < NPTS / 64; tile += gridDim.x) {
        int p0g = tile * 64;
        {
            const float4* x4 = (const float4*)g_x + (size_t)p0g * 16;
            float4* sx4 = (float4*)sx;
#pragma unroll
            for (int i = 0; i < 4; i++) sx4[tid + i * 256] = x4[tid + i * 256];
        }
        __syncthreads();
        float po[4] = {0.f, 0.f, 0.f, 0.f};
#pragma unroll
        for (int jb = 0; jb < 4; jb++) {
            int j0 = jb * 64 + tx * 4;
            float acc[4][4];
#pragma unroll
            for (int r = 0; r < 4; r++)
#pragma unroll
                for (int s = 0; s < 4; s++) acc[r][s] = 0.f;
#pragma unroll 4
            for (int kc = 0; kc < 64; kc += 4) {
                float a[4][4];
#pragma unroll
                for (int r = 0; r < 4; r++) {
                    float4 t = *(const float4*)&sx[(p0 + r) * 64 + kc];
                    a[r][0] = t.x; a[r][1] = t.y; a[r][2] = t.z; a[r][3] = t.w;
                }
#pragma unroll
                for (int kk = 0; kk < 4; kk++) {
                    float4 w = *(const float4*)&w1T[(kc + kk) * 260 + j0];
#pragma unroll
                    for (int r = 0; r < 4; r++) {
                        acc[r][0] = fmaf(a[r][kk], w.x, acc[r][0]);
                        acc[r][1] = fmaf(a[r][kk], w.y, acc[r][1]);
                        acc[r][2] = fmaf(a[r][kk], w.z, acc[r][2]);
                        acc[r][3] = fmaf(a[r][kk], w.w, acc[r][3]);
                    }
                }
            }
#pragma unroll
            for (int s = 0; s < 4; s++) {
                float bv = b1[j0 + s];
                float wv = w2[j0 + s];
#pragma unroll
                for (int r = 0; r < 4; r++)
                    po[r] = fmaf(wv, gelu_exact(acc[r][s] + bv), po[r]);
            }
        }
#pragma unroll
        for (int off = 8; off; off >>= 1) {
#pragma unroll
            for (int r = 0; r < 4; r++)
                po[r] += __shfl_down_sync(0xffffffffu, po[r], off);
        }
        if (tx == 0) {
#pragma unroll
            for (int r = 0; r < 4; r++) out[p0g + p0 + r] = po[r] + qb;
        }
        __syncthreads();
    }
}

// ---------------- host launcher ----------------
extern "C" void kernel_launch(void* const* d_in, const int* in_sizes, int n_in,
                              void* d_out, int out_size) {
    const float* x_in   = (const float*)d_in[0];
    const float* p_w    = (const float*)d_in[1];
    const float* p_b    = (const float*)d_in[2];
    const float* W_LC   = (const float*)d_in[3];
    const float* W_LR   = (const float*)d_in[4];
    const float* mlp_w1 = (const float*)d_in[5];
    const float* mlp_b1 = (const float*)d_in[6];
    const float* mlp_w2 = (const float*)d_in[7];
    const float* mlp_b2 = (const float*)d_in[8];
    const float* w_w    = (const float*)d_in[9];
    const float* w_b    = (const float*)d_in[10];
    const float* q_w1   = (const float*)d_in[11];
    const float* q_b1   = (const float*)d_in[12];
    const float* q_w2   = (const float*)d_in[13];
    const float* q_b2   = (const float*)d_in[14];
    float* out = (float*)d_out;

    const int FUSE_SMEM = FUSE_SMEMF * 4;               // 113152 B
    const int QMLP_SMEM = (64 * 260 + 4096) * 4;        // 82944 B
    cudaFuncSetAttribute(fuse_k, cudaFuncAttributeMaxDynamicSharedMemorySize, FUSE_SMEM);
    cudaFuncSetAttribute(qmlp_k, cudaFuncAttributeMaxDynamicSharedMemorySize, QMLP_SMEM);

    init_tw_k<<<1, 256>>>();
    transpose_k<<<dim3(3, 128, NLAY),  dim3(32, 8)>>>(W_LC, 4096, 96,  0);
    transpose_k<<<dim3(31, 128, NLAY), dim3(32, 8)>>>(W_LR, 4096, 968, 1);

    lift_k<<<NPTS / 64, 256>>>(x_in, p_w, p_b);

    for (int l = 0; l < NLAY; l++) {
        fwdz_k<<<BB * S1D * S2D / 8, 256>>>();
        fwdy_k<<<BB * S2D * TTD, 96>>>();
        fwdx_k<<<BB * MMD * TTD, 96>>>();
        mix_k <<<MMD * MMD * TTD, 128>>>(l);
        invy_k<<<BB * MMD * TTD, 256>>>();
        invx_k<<<BB * S1D * TTD, 256>>>();
        fuse_k<<<592, 256, FUSE_SMEM>>>(
            mlp_w1 + l * 4096, mlp_b1 + l * 64,
            mlp_w2 + l * 4096, mlp_b2 + l * 64,
            w_w + l * 4096,    w_b + l * 64,
            (l < NLAY - 1) ? 1 : 0);
    }

    qmlp_k<<<592, 256, QMLP_SMEM>>>(q_w1, q_b1, q_w2, q_b2, out);
}

// round 5
// speedup vs baseline: 2.3114x; 1.1177x over previous
#include <cuda_runtime.h>
#include <math.h>

#define BB 2
#define S1D 64
#define S2D 64
#define S3D 40
#define CHW 64
#define MMD 23
#define TTD 8
#define NPTS (BB*S1D*S2D*S3D)   // 327680
#define NLAY 4

// ---------------- device scratch (static, allocation-free, 16B aligned) ----------------
__device__ __align__(16) float g_x [NPTS*CHW];
__device__ __align__(16) float g_Ar[BB*S1D*S2D*TTD*CHW];
__device__ __align__(16) float g_Ai[BB*S1D*S2D*TTD*CHW];
__device__ __align__(16) float g_Br[BB*MMD*S2D*TTD*CHW];
__device__ __align__(16) float g_Bi[BB*MMD*S2D*TTD*CHW];
__device__ __align__(16) float g_Xr[BB*MMD*MMD*TTD*CHW];
__device__ __align__(16) float g_Xi[BB*MMD*MMD*TTD*CHW];
__device__ __align__(16) float g_Yr[BB*MMD*MMD*TTD*CHW];
__device__ __align__(16) float g_Yi[BB*MMD*MMD*TTD*CHW];
__device__ __align__(16) float g_wlc[NLAY*12*TTD*CHW*CHW];     // [l][a*8+kz][i*64+o]
__device__ __align__(16) float g_wlr[NLAY*11*11*TTD*CHW*CHW];  // [l][(p*11+q)*8+kz][i*64+o]

// twiddle tables
__device__ __align__(16) float t_fz[S3D][16];      // [n][2k]=cos, [2k+1]=sin
__device__ __align__(16) float t_iz[S3D][16];      // scaled inverse-z
__device__ __align__(16) float t_fy[S1D][48];      // [n][ky]=cos (pad 24), [n][24+ky]=sin
__device__ __align__(16) float t_iy[MMD][128];     // [ky][n]=cos, [ky][64+n]=sin

__device__ __forceinline__ float4 f4fma(float4 a, float s, float4 acc) {
    acc.x = fmaf(a.x, s, acc.x); acc.y = fmaf(a.y, s, acc.y);
    acc.z = fmaf(a.z, s, acc.z); acc.w = fmaf(a.w, s, acc.w);
    return acc;
}
__device__ __forceinline__ float4 f4zero() { return make_float4(0.f, 0.f, 0.f, 0.f); }

__device__ __forceinline__ float gelu_exact(float z) {
    return 0.5f * z * (1.0f + erff(z * 0.70710678118654752f));
}

// ---------------- twiddle init ----------------
__global__ void init_tw_k() {
    int tid = threadIdx.x;   // 256
    for (int i = tid; i < TTD * S3D; i += 256) {
        int k = i / S3D, n = i % S3D;
        float s, c;
        sincospif((float)((2 * k * n) % 80) * (1.0f / 40.0f), &s, &c);
        t_fz[n][2 * k] = c; t_fz[n][2 * k + 1] = s;
        float sc = (k == 0 ? 1.0f : 2.0f) * (1.0f / 163840.0f);
        t_iz[n][2 * k] = c * sc; t_iz[n][2 * k + 1] = s * sc;
    }
    for (int i = tid; i < S1D * 24; i += 256) {
        int n = i / 24, ky = i % 24;
        float c = 0.f, s = 0.f;
        if (ky < MMD) {
            int t = ((ky - 11) * n) & 63;
            sincospif((float)t * (1.0f / 32.0f), &s, &c);
        }
        t_fy[n][ky] = c; t_fy[n][24 + ky] = s;
        if (ky < MMD) { t_iy[ky][n] = c; t_iy[ky][64 + n] = s; }
    }
}

// ---------------- weight transpose: [l][io][m] -> [l][m][io] ----------------
__global__ void transpose_k(const float* __restrict__ src, int rows, int cols, int which) {
    __shared__ float tile[32][33];
    float* dst = which ? g_wlr : g_wlc;
    int l = blockIdx.z;
    const float* s = src + (size_t)l * rows * cols;
    float* d = dst + (size_t)l * rows * cols;
    int c0 = blockIdx.x * 32, r0 = blockIdx.y * 32;
    int tx = threadIdx.x;
    for (int dy = threadIdx.y; dy < 32; dy += 8) {
        int r = r0 + dy, c = c0 + tx;
        if (r < rows && c < cols) tile[dy][tx] = s[(size_t)r * cols + c];
    }
    __syncthreads();
    for (int dy = threadIdx.y; dy < 32; dy += 8) {
        int c = c0 + dy, r = r0 + tx;
        if (r < rows && c < cols) d[(size_t)c * rows + r] = tile[tx][dy];
    }
}

// ---------------- lift: smem-staged, float4 everywhere ----------------
__global__ void lift_k(const float* __restrict__ xin, const float* __restrict__ pw,
                       const float* __restrict__ pb) {
    __shared__ float wT[13 * 64];   // [i][c]
    __shared__ float xs[64 * 10];
    int tid = threadIdx.x;          // 256
    for (int j = tid; j < 832; j += 256) {
        int c = j / 13, i = j % 13;
        wT[i * 64 + c] = pw[j];
    }
    int p0g = blockIdx.x * 64;
    for (int j = tid; j < 640; j += 256) xs[j] = xin[(size_t)p0g * 10 + j];
    __syncthreads();

    int c0 = (tid & 15) * 4;
    float4 pb4 = *(const float4*)&pb[c0];
    float4 w10 = *(const float4*)&wT[10 * 64 + c0];
    float4 w11 = *(const float4*)&wT[11 * 64 + c0];
    float4 w12 = *(const float4*)&wT[12 * 64 + c0];
#pragma unroll
    for (int pass = 0; pass < 4; pass++) {
        int pl = pass * 16 + (tid >> 4);
        int p = p0g + pl;
        int n3 = p % S3D;
        int r = p / S3D;
        int n2 = r & 63; r >>= 6;
        int n1 = r & 63;
        float4 acc = pb4;
        acc = f4fma(w10, n1 * (1.0f / 63.0f), acc);
        acc = f4fma(w11, n2 * (1.0f / 63.0f), acc);
        acc = f4fma(w12, n3 * (1.0f / 39.0f), acc);
        const float* xp = &xs[pl * 10];
#pragma unroll
        for (int i = 0; i < 10; i++) {
            float4 wv = *(const float4*)&wT[i * 64 + c0];
            acc = f4fma(wv, xp[i], acc);
        }
        *(float4*)&g_x[(size_t)p * 64 + c0] = acc;
    }
}

// ---------------- forward z-DFT: real 40 -> complex 8 ----------------
__global__ void fwdz_k() {
    __shared__ __align__(16) float tw[S3D][16];
    int tid = threadIdx.x;  // 256, 8 columns per block (one per warp)
    for (int i = tid; i < S3D * 16; i += 256) tw[i >> 4][i & 15] = t_fz[i >> 4][i & 15];
    __syncthreads();
    int col = blockIdx.x * 8 + (tid >> 5);
    int lane = tid & 31;
    int cg = lane & 15, kzg = lane >> 4;
    const float4* xp = (const float4*)g_x + (size_t)col * 640 + cg;
    float4 ar[4], ai[4];
#pragma unroll
    for (int j = 0; j < 4; j++) { ar[j] = f4zero(); ai[j] = f4zero(); }
#pragma unroll 8
    for (int n = 0; n < S3D; n++) {
        float4 v = xp[n * 16];
        float4 t0 = *(const float4*)&tw[n][kzg * 8];
        float4 t1 = *(const float4*)&tw[n][kzg * 8 + 4];
        ar[0] = f4fma(v,  t0.x, ar[0]); ai[0] = f4fma(v, -t0.y, ai[0]);
        ar[1] = f4fma(v,  t0.z, ar[1]); ai[1] = f4fma(v, -t0.w, ai[1]);
        ar[2] = f4fma(v,  t1.x, ar[2]); ai[2] = f4fma(v, -t1.y, ai[2]);
        ar[3] = f4fma(v,  t1.z, ar[3]); ai[3] = f4fma(v, -t1.w, ai[3]);
    }
    float4* Ar4 = (float4*)g_Ar;
    float4* Ai4 = (float4*)g_Ai;
    size_t base = (size_t)col * 128 + kzg * 64 + cg;
#pragma unroll
    for (int j = 0; j < 4; j++) {
        Ar4[base + j * 16] = ar[j];
        Ai4[base + j * 16] = ai[j];
    }
}

// ---------------- forward y-DFT: n1 (64) -> ky (23) ----------------
__global__ void fwdy_k() {
    __shared__ __align__(16) float Sr[S1D][CHW], Si[S1D][CHW];
    __shared__ __align__(16) float twf[S1D][48];
    int tid = threadIdx.x;  // 96
    int blk = blockIdx.x;
    int kz = blk & 7, rest = blk >> 3;
    int n2 = rest & 63, b = rest >> 6;
    const float4* Ar4 = (const float4*)g_Ar;
    const float4* Ai4 = (const float4*)g_Ai;
    for (int i = tid; i < 1024; i += 96) {
        int n1 = i >> 4, c4 = i & 15;
        size_t g4 = ((((size_t)b * S1D + n1) * S2D + n2) * TTD + kz) * 16 + c4;
        *(float4*)&Sr[n1][c4 * 4] = Ar4[g4];
        *(float4*)&Si[n1][c4 * 4] = Ai4[g4];
    }
    for (int i = tid; i < 768; i += 96) ((float4*)twf)[i] = ((const float4*)t_fy)[i];
    __syncthreads();
    int cg = tid & 15, kg = tid >> 4;   // kg 0..5
    float4 ar[4], ai[4];
#pragma unroll
    for (int j = 0; j < 4; j++) { ar[j] = f4zero(); ai[j] = f4zero(); }
#pragma unroll 4
    for (int n = 0; n < S1D; n++) {
        float4 xr = *(const float4*)&Sr[n][cg * 4];
        float4 xi = *(const float4*)&Si[n][cg * 4];
        float4 tc = *(const float4*)&twf[n][kg * 4];
        float4 ts = *(const float4*)&twf[n][24 + kg * 4];
        ar[0]=f4fma(xr,tc.x,ar[0]); ar[0]=f4fma(xi,ts.x,ar[0]); ai[0]=f4fma(xi,tc.x,ai[0]); ai[0]=f4fma(xr,-ts.x,ai[0]);
        ar[1]=f4fma(xr,tc.y,ar[1]); ar[1]=f4fma(xi,ts.y,ar[1]); ai[1]=f4fma(xi,tc.y,ai[1]); ai[1]=f4fma(xr,-ts.y,ai[1]);
        ar[2]=f4fma(xr,tc.z,ar[2]); ar[2]=f4fma(xi,ts.z,ar[2]); ai[2]=f4fma(xi,tc.z,ai[2]); ai[2]=f4fma(xr,-ts.z,ai[2]);
        ar[3]=f4fma(xr,tc.w,ar[3]); ar[3]=f4fma(xi,ts.w,ar[3]); ai[3]=f4fma(xi,tc.w,ai[3]); ai[3]=f4fma(xr,-ts.w,ai[3]);
    }
    float4* Br4 = (float4*)g_Br;
    float4* Bi4 = (float4*)g_Bi;
#pragma unroll
    for (int j = 0; j < 4; j++) {
        int ky = kg * 4 + j;
        if (ky < MMD) {
            size_t g4 = ((((size_t)b * MMD + ky) * S2D + n2) * TTD + kz) * 16 + cg;
            Br4[g4] = ar[j]; Bi4[g4] = ai[j];
        }
    }
}

// ---------------- forward x-DFT: n2 (64) -> kx (23) ----------------
__global__ void fwdx_k() {
    __shared__ __align__(16) float Sr[S2D][CHW], Si[S2D][CHW];
    __shared__ __align__(16) float twf[S2D][48];
    int tid = threadIdx.x;  // 96
    int blk = blockIdx.x;
    int kz = blk & 7, rest = blk >> 3;
    int ky = rest % MMD, b = rest / MMD;
    const float4* Br4 = (const float4*)g_Br;
    const float4* Bi4 = (const float4*)g_Bi;
    for (int i = tid; i < 1024; i += 96) {
        int n2 = i >> 4, c4 = i & 15;
        size_t g4 = ((((size_t)b * MMD + ky) * S2D + n2) * TTD + kz) * 16 + c4;
        *(float4*)&Sr[n2][c4 * 4] = Br4[g4];
        *(float4*)&Si[n2][c4 * 4] = Bi4[g4];
    }
    for (int i = tid; i < 768; i += 96) ((float4*)twf)[i] = ((const float4*)t_fy)[i];
    __syncthreads();
    int cg = tid & 15, kg = tid >> 4;
    float4 ar[4], ai[4];
#pragma unroll
    for (int j = 0; j < 4; j++) { ar[j] = f4zero(); ai[j] = f4zero(); }
#pragma unroll 4
    for (int n = 0; n < S2D; n++) {
        float4 xr = *(const float4*)&Sr[n][cg * 4];
        float4 xi = *(const float4*)&Si[n][cg * 4];
        float4 tc = *(const float4*)&twf[n][kg * 4];
        float4 ts = *(const float4*)&twf[n][24 + kg * 4];
        ar[0]=f4fma(xr,tc.x,ar[0]); ar[0]=f4fma(xi,ts.x,ar[0]); ai[0]=f4fma(xi,tc.x,ai[0]); ai[0]=f4fma(xr,-ts.x,ai[0]);
        ar[1]=f4fma(xr,tc.y,ar[1]); ar[1]=f4fma(xi,ts.y,ar[1]); ai[1]=f4fma(xi,tc.y,ai[1]); ai[1]=f4fma(xr,-ts.y,ai[1]);
        ar[2]=f4fma(xr,tc.z,ar[2]); ar[2]=f4fma(xi,ts.z,ar[2]); ai[2]=f4fma(xi,tc.z,ai[2]); ai[2]=f4fma(xr,-ts.z,ai[2]);
        ar[3]=f4fma(xr,tc.w,ar[3]); ar[3]=f4fma(xi,ts.w,ar[3]); ai[3]=f4fma(xi,tc.w,ai[3]); ai[3]=f4fma(xr,-ts.w,ai[3]);
    }
    float4* Xr4 = (float4*)g_Xr;
    float4* Xi4 = (float4*)g_Xi;
#pragma unroll
    for (int j = 0; j < 4; j++) {
        int kx = kg * 4 + j;
        if (kx < MMD) {
            size_t g4 = ((((size_t)b * MMD + ky) * MMD + kx) * TTD + kz) * 16 + cg;
            Xr4[g4] = ar[j]; Xi4[g4] = ai[j];
        }
    }
}

// --------- mode -> (sel, a, b) mapping replicating _spectral_weights ---------
__device__ __forceinline__ void map_mode(int y, int x, int& sel, int& ia, int& ib) {
    int yy, s;
    if (x >= 11) { yy = y; s = x - 11; }
    else         { yy = 22 - y; s = 11 - x; }
    int r, t;
    if (yy < 12) {
        if (s == 0) { sel = 0; ia = 11 - yy; ib = 0; return; }
        r = s - 1; t = 11 - yy;
    } else { r = yy - 12; t = s; }
    if (t == 0) { sel = 0; ia = r + 1; ib = 0; }
    else        { sel = 1; ia = r;     ib = t - 1; }
}

// -------- per-mode 64x64 channel mix, fused with W1 (spectral-space mlp GEMM1) --------
__global__ void mix_k(int l, const float* __restrict__ w1) {
    __shared__ __align__(16) float xs[BB][2][CHW];
    __shared__ __align__(16) float red[8][256];
    __shared__ float w1s[64 * 65];   // [i][o], skewed
    __shared__ float ys[256];
    int m = blockIdx.x;
    int kz = m % TTD, x = (m / TTD) % MMD, y = m / (TTD * MMD);
    int sel, ia, ib;
    map_mode(y, x, sel, ia, ib);
    const float* wp;
    if (sel == 0) wp = g_wlc + (((size_t)l * 12 + ia) * TTD + kz) * (CHW * CHW);
    else          wp = g_wlr + (((size_t)l * 121 + ia * 11 + ib) * TTD + kz) * (CHW * CHW);
    int tid = threadIdx.x;   // 128
    // load w1 [o][i] -> w1s [i][o] (skewed stride 65)
    for (int j = tid; j < 4096; j += 128)
        w1s[(j & 63) * 65 + (j >> 6)] = w1[j];
    {
        int b = tid >> 6, c = tid & 63;
        size_t g = ((((size_t)b * MMD + y) * MMD + x) * TTD + kz) * CHW + c;
        xs[b][0][c] = g_Xr[g];
        xs[b][1][c] = g_Xi[g];
    }
    __syncthreads();
    int ks = tid >> 4, og = tid & 15;
    float4 a00 = f4zero(), a01 = f4zero(), a10 = f4zero(), a11 = f4zero();
    const float4* wp4 = (const float4*)wp;
#pragma unroll
    for (int it = 0; it < 8; it++) {
        int i = ks * 8 + it;
        float4 w = wp4[i * 16 + og];
        a00 = f4fma(w, xs[0][0][i], a00);
        a01 = f4fma(w, xs[0][1][i], a01);
        a10 = f4fma(w, xs[1][0][i], a10);
        a11 = f4fma(w, xs[1][1][i], a11);
    }
    *(float4*)&red[ks][  0 + og * 4] = a00;
    *(float4*)&red[ks][ 64 + og * 4] = a01;
    *(float4*)&red[ks][128 + og * 4] = a10;
    *(float4*)&red[ks][192 + og * 4] = a11;
    __syncthreads();
    for (int v = tid; v < 256; v += 128) {
        float s = 0.f;
#pragma unroll
        for (int k = 0; k < 8; k++) s += red[k][v];
        ys[v] = s;
    }
    __syncthreads();
    // apply W1 in spectral space: out[o] = sum_i w1[o,i] * ys[.,i]
    for (int v = tid; v < 256; v += 128) {
        int o = v & 63;
        int base = v & 192;       // b*128 + ri*64
        float acc = 0.f;
#pragma unroll 8
        for (int i = 0; i < 64; i++)
            acc = fmaf(w1s[i * 65 + o], ys[base + i], acc);
        int b = v >> 7, ri = (v >> 6) & 1;
        size_t g = ((((size_t)b * MMD + y) * MMD + x) * TTD + kz) * CHW + o;
        if (ri) g_Yi[g] = acc; else g_Yr[g] = acc;
    }
}

// ---------------- inverse y: ky (23) -> n1 (64) ----------------
__global__ void invy_k() {
    __shared__ __align__(16) float Sr[MMD][CHW], Si[MMD][CHW];
    __shared__ __align__(16) float twi[MMD][128];
    int tid = threadIdx.x;  // 256
    int blk = blockIdx.x;
    int kz = blk & 7, rest = blk >> 3;
    int kx = rest % MMD, b = rest / MMD;
    const float4* Yr4 = (const float4*)g_Yr;
    const float4* Yi4 = (const float4*)g_Yi;
    for (int i = tid; i < MMD * 16; i += 256) {
        int ky = i >> 4, c4 = i & 15;
        size_t g4 = ((((size_t)b * MMD + ky) * MMD + kx) * TTD + kz) * 16 + c4;
        *(float4*)&Sr[ky][c4 * 4] = Yr4[g4];
        *(float4*)&Si[ky][c4 * 4] = Yi4[g4];
    }
    for (int i = tid; i < 736; i += 256) ((float4*)twi)[i] = ((const float4*)t_iy)[i];
    __syncthreads();
    int cg = tid & 15, ng = tid >> 4;
    int n0 = ng * 4;
    float4 ar[4], ai[4];
#pragma unroll
    for (int j = 0; j < 4; j++) { ar[j] = f4zero(); ai[j] = f4zero(); }
#pragma unroll
    for (int ky = 0; ky < MMD; ky++) {
        float4 xr = *(const float4*)&Sr[ky][cg * 4];
        float4 xi = *(const float4*)&Si[ky][cg * 4];
        float4 tc = *(const float4*)&twi[ky][n0];
        float4 ts = *(const float4*)&twi[ky][64 + n0];
        ar[0]=f4fma(xr,tc.x,ar[0]); ar[0]=f4fma(xi,-ts.x,ar[0]); ai[0]=f4fma(xr,ts.x,ai[0]); ai[0]=f4fma(xi,tc.x,ai[0]);
        ar[1]=f4fma(xr,tc.y,ar[1]); ar[1]=f4fma(xi,-ts.y,ar[1]); ai[1]=f4fma(xr,ts.y,ai[1]); ai[1]=f4fma(xi,tc.y,ai[1]);
        ar[2]=f4fma(xr,tc.z,ar[2]); ar[2]=f4fma(xi,-ts.z,ar[2]); ai[2]=f4fma(xr,ts.z,ai[2]); ai[2]=f4fma(xi,tc.z,ai[2]);
        ar[3]=f4fma(xr,tc.w,ar[3]); ar[3]=f4fma(xi,-ts.w,ar[3]); ai[3]=f4fma(xr,ts.w,ai[3]); ai[3]=f4fma(xi,tc.w,ai[3]);
    }
    float4* Br4 = (float4*)g_Br;
    float4* Bi4 = (float4*)g_Bi;
#pragma unroll
    for (int j = 0; j < 4; j++) {
        int n1 = n0 + j;
        size_t g4 = ((((size_t)b * S1D + n1) * MMD + kx) * TTD + kz) * 16 + cg;
        Br4[g4] = ar[j]; Bi4[g4] = ai[j];
    }
}

// ---------------- inverse x: kx (23) -> n2 (64) ----------------
__global__ void invx_k() {
    __shared__ __align__(16) float Sr[MMD][CHW], Si[MMD][CHW];
    __shared__ __align__(16) float twi[MMD][128];
    int tid = threadIdx.x;  // 256
    int blk = blockIdx.x;
    int kz = blk & 7, rest = blk >> 3;
    int n1 = rest & 63, b = rest >> 6;
    const float4* Br4 = (const float4*)g_Br;
    const float4* Bi4 = (const float4*)g_Bi;
    for (int i = tid; i < MMD * 16; i += 256) {
        int kx = i >> 4, c4 = i & 15;
        size_t g4 = ((((size_t)b * S1D + n1) * MMD + kx) * TTD + kz) * 16 + c4;
        *(float4*)&Sr[kx][c4 * 4] = Br4[g4];
        *(float4*)&Si[kx][c4 * 4] = Bi4[g4];
    }
    for (int i = tid; i < 736; i += 256) ((float4*)twi)[i] = ((const float4*)t_iy)[i];
    __syncthreads();
    int cg = tid & 15, ng = tid >> 4;
    int n0 = ng * 4;
    float4 ar[4], ai[4];
#pragma unroll
    for (int j = 0; j < 4; j++) { ar[j] = f4zero(); ai[j] = f4zero(); }
#pragma unroll
    for (int kx = 0; kx < MMD; kx++) {
        float4 xr = *(const float4*)&Sr[kx][cg * 4];
        float4 xi = *(const float4*)&Si[kx][cg * 4];
        float4 tc = *(const float4*)&twi[kx][n0];
        float4 ts = *(const float4*)&twi[kx][64 + n0];
        ar[0]=f4fma(xr,tc.x,ar[0]); ar[0]=f4fma(xi,-ts.x,ar[0]); ai[0]=f4fma(xr,ts.x,ai[0]); ai[0]=f4fma(xi,tc.x,ai[0]);
        ar[1]=f4fma(xr,tc.y,ar[1]); ar[1]=f4fma(xi,-ts.y,ar[1]); ai[1]=f4fma(xr,ts.y,ai[1]); ai[1]=f4fma(xi,tc.y,ai[1]);
        ar[2]=f4fma(xr,tc.z,ar[2]); ar[2]=f4fma(xi,-ts.z,ar[2]); ai[2]=f4fma(xr,ts.z,ai[2]); ai[2]=f4fma(xi,tc.z,ai[2]);
        ar[3]=f4fma(xr,tc.w,ar[3]); ar[3]=f4fma(xi,-ts.w,ar[3]); ai[3]=f4fma(xr,ts.w,ai[3]); ai[3]=f4fma(xi,tc.w,ai[3]);
    }
    float4* Ar4 = (float4*)g_Ar;
    float4* Ai4 = (float4*)g_Ai;
#pragma unroll
    for (int j = 0; j < 4; j++) {
        int n2 = n0 + j;
        size_t g4 = ((((size_t)b * S1D + n1) * S2D + n2) * TTD + kz) * 16 + cg;
        Ar4[g4] = ar[j]; Ai4[g4] = ai[j];
    }
}

// ===== fused invz (already W1-applied) + gelu + GEMM2 + skip GEMM, persistent =====
// smem floats: w2T[4096] wwT[4096] sX[5120] sA[5120] dD[2048] tw[640] = 21120 floats
#define FUSE_SMEMF (4096*2 + 5120*2 + 2048 + 640)   // 21120 floats = 84480 B
__global__ void __launch_bounds__(256, 2)
fuse_k(const float* __restrict__ b1,
       const float* __restrict__ w2, const float* __restrict__ b2,
       const float* __restrict__ ww, const float* __restrict__ wb,
       int do_relu) {
    extern __shared__ float sm[];
    float* w2T = sm;
    float* wwT = sm + 4096;
    float* sX  = sm + 8192;
    float* sA  = sm + 13312;
    float* dDf = sm + 18432;
    float* tw  = sm + 20480;
    int tx = threadIdx.x & 15, ty = threadIdx.x >> 4;
    int tid = threadIdx.x;

    for (int i = tid; i < 4096; i += 256) {
        int o = i >> 6, ic = i & 63;
        w2T[ic * 64 + o] = w2[i];
        wwT[ic * 64 + o] = ww[i];
    }
    for (int i = tid; i < 640; i += 256) tw[i] = ((const float*)t_iz)[i];

    int o0 = tx * 4, q0 = ty * 5;
    float bbv[4];
#pragma unroll
    for (int s = 0; s < 4; s++) bbv[s] = b2[o0 + s] + wb[o0 + s];
    // b1 for invz epilogue channels (cg = tid & 15 -> channels cg*4..cg*4+3)
    float4 b1c = *(const float4*)&b1[(tid & 15) * 4];
    __syncthreads();

    const float4* Ar4 = (const float4*)g_Ar;
    const float4* Ai4 = (const float4*)g_Ai;
    float4* dD = (float4*)dDf;

    for (int pair = blockIdx.x; pair < 4096; pair += gridDim.x) {
        size_t pbase = (size_t)pair * 80;
        size_t colg = (size_t)pair * 2;
        dD[tid]       = Ar4[colg * 128 + tid];
        dD[256 + tid] = Ai4[colg * 128 + tid];
        {
            const float4* gx4 = (const float4*)g_x + pbase * 16;
            float4* sX4 = (float4*)sX;
#pragma unroll
            for (int i = 0; i < 5; i++) sX4[tid + i * 256] = gx4[tid + i * 256];
        }
        __syncthreads();

        // ---- invz + bias + gelu: sA[80][64] = gelu(W1*s1 + b1) ----
        {
            int cg = tid & 15, rg = tid >> 4;
            int ccprev = -1;
            float4 dr[8], di[8];
#pragma unroll
            for (int r = 0; r < 5; r++) {
                int row = rg * 5 + r;
                int cc = (row >= 40) ? 1 : 0;
                int n3 = row - cc * 40;
                if (cc != ccprev) {
#pragma unroll
                    for (int k = 0; k < 8; k++) {
                        dr[k] = dD[cc * 128 + k * 16 + cg];
                        di[k] = dD[256 + cc * 128 + k * 16 + cg];
                    }
                    ccprev = cc;
                }
                float4 t0 = *(const float4*)&tw[n3 * 16 + 0];
                float4 t1 = *(const float4*)&tw[n3 * 16 + 4];
                float4 t2 = *(const float4*)&tw[n3 * 16 + 8];
                float4 t3 = *(const float4*)&tw[n3 * 16 + 12];
                float4 acc = f4zero();
                acc = f4fma(dr[0],  t0.x, acc); acc = f4fma(di[0], -t0.y, acc);
                acc = f4fma(dr[1],  t0.z, acc); acc = f4fma(di[1], -t0.w, acc);
                acc = f4fma(dr[2],  t1.x, acc); acc = f4fma(di[2], -t1.y, acc);
                acc = f4fma(dr[3],  t1.z, acc); acc = f4fma(di[3], -t1.w, acc);
                acc = f4fma(dr[4],  t2.x, acc); acc = f4fma(di[4], -t2.y, acc);
                acc = f4fma(dr[5],  t2.z, acc); acc = f4fma(di[5], -t2.w, acc);
                acc = f4fma(dr[6],  t3.x, acc); acc = f4fma(di[6], -t3.y, acc);
                acc = f4fma(dr[7],  t3.z, acc); acc = f4fma(di[7], -t3.w, acc);
                float4 h;
                h.x = gelu_exact(acc.x + b1c.x);
                h.y = gelu_exact(acc.y + b1c.y);
                h.z = gelu_exact(acc.z + b1c.z);
                h.w = gelu_exact(acc.w + b1c.w);
                *(float4*)&sA[row * 64 + cg * 4] = h;
            }
        }
        __syncthreads();

        // ---- GEMM2 (W2*H) + GEMM3 (Ww*X) ----
        float acc[5][4];
#pragma unroll
        for (int r = 0; r < 5; r++)
#pragma unroll
            for (int s = 0; s < 4; s++) acc[r][s] = 0.f;
#pragma unroll 4
        for (int ic = 0; ic < 64; ic += 4) {
            float a[5][4];
#pragma unroll
            for (int r = 0; r < 5; r++) {
                float4 t = *(const float4*)&sA[(q0 + r) * 64 + ic];
                a[r][0] = t.x; a[r][1] = t.y; a[r][2] = t.z; a[r][3] = t.w;
            }
#pragma unroll
            for (int kk = 0; kk < 4; kk++) {
                float4 w = *(const float4*)&w2T[(ic + kk) * 64 + o0];
#pragma unroll
                for (int r = 0; r < 5; r++) {
                    acc[r][0] = fmaf(a[r][kk], w.x, acc[r][0]);
                    acc[r][1] = fmaf(a[r][kk], w.y, acc[r][1]);
                    acc[r][2] = fmaf(a[r][kk], w.z, acc[r][2]);
                    acc[r][3] = fmaf(a[r][kk], w.w, acc[r][3]);
                }
            }
        }
#pragma unroll 4
        for (int ic = 0; ic < 64; ic += 4) {
            float a[5][4];
#pragma unroll
            for (int r = 0; r < 5; r++) {
                float4 t = *(const float4*)&sX[(q0 + r) * 64 + ic];
                a[r][0] = t.x; a[r][1] = t.y; a[r][2] = t.z; a[r][3] = t.w;
            }
#pragma unroll
            for (int kk = 0; kk < 4; kk++) {
                float4 w = *(const float4*)&wwT[(ic + kk) * 64 + o0];
#pragma unroll
                for (int r = 0; r < 5; r++) {
                    acc[r][0] = fmaf(a[r][kk], w.x, acc[r][0]);
                    acc[r][1] = fmaf(a[r][kk], w.y, acc[r][1]);
                    acc[r][2] = fmaf(a[r][kk], w.z, acc[r][2]);
                    acc[r][3] = fmaf(a[r][kk], w.w, acc[r][3]);
                }
            }
        }
#pragma unroll
        for (int r = 0; r < 5; r++) {
            float4 v;
            v.x = acc[r][0] + bbv[0]; v.y = acc[r][1] + bbv[1];
            v.z = acc[r][2] + bbv[2]; v.w = acc[r][3] + bbv[3];
            if (do_relu) {
                v.x = fmaxf(v.x, 0.f); v.y = fmaxf(v.y, 0.f);
                v.z = fmaxf(v.z, 0.f); v.w = fmaxf(v.w, 0.f);
            }
            *(float4*)&g_x[(pbase + q0 + r) * 64 + o0] = v;
        }
        __syncthreads();
    }
}

// ---------------- final query MLP: 64 -> 256 (gelu) -> 1, persistent ----------------
__global__ void __launch_bounds__(256, 2)
qmlp_k(const float* __restrict__ w1, const float* __restrict__ b1,
       const float* __restrict__ w2, const float* __restrict__ b2,
       float* __restrict__ out) {
    extern __shared__ float sm[];
    float* w1T = sm;              // [k 64][j 260-pad]
    float* sx  = sm + 64 * 260;   // [p][64]
    int tx = threadIdx.x & 15, ty = threadIdx.x >> 4;
    int tid = threadIdx.x;
    for (int i = tid; i < 256 * 64; i += 256) {
        int j = i >> 6, k = i & 63;
        w1T[k * 260 + j] = w1[i];
    }
    __syncthreads();
    float qb = b2[0];
    int p0 = ty * 4;

    for (int tile = blockIdx.x; tile < NPTS / 64; tile += gridDim.x) {
        int p0g = tile * 64;
        {
            const float4* x4 = (const float4*)g_x + (size_t)p0g * 16;
            float4* sx4 = (float4*)sx;
#pragma unroll
            for (int i = 0; i < 4; i++) sx4[tid + i * 256] = x4[tid + i * 256];
        }
        __syncthreads();
        float po[4] = {0.f, 0.f, 0.f, 0.f};
#pragma unroll
        for (int jb = 0; jb < 4; jb++) {
            int j0 = jb * 64 + tx * 4;
            float acc[4][4];
#pragma unroll
            for (int r = 0; r < 4; r++)
#pragma unroll
                for (int s = 0; s < 4; s++) acc[r][s] = 0.f;
#pragma unroll 4
            for (int kc = 0; kc < 64; kc += 4) {
                float a[4][4];
#pragma unroll
                for (int r = 0; r < 4; r++) {
                    float4 t = *(const float4*)&sx[(p0 + r) * 64 + kc];
                    a[r][0] = t.x; a[r][1] = t.y; a[r][2] = t.z; a[r][3] = t.w;
                }
#pragma unroll
                for (int kk = 0; kk < 4; kk++) {
                    float4 w = *(const float4*)&w1T[(kc + kk) * 260 + j0];
#pragma unroll
                    for (int r = 0; r < 4; r++) {
                        acc[r][0] = fmaf(a[r][kk], w.x, acc[r][0]);
                        acc[r][1] = fmaf(a[r][kk], w.y, acc[r][1]);
                        acc[r][2] = fmaf(a[r][kk], w.z, acc[r][2]);
                        acc[r][3] = fmaf(a[r][kk], w.w, acc[r][3]);
                    }
                }
            }
#pragma unroll
            for (int s = 0; s < 4; s++) {
                float bv = b1[j0 + s];
                float wv = w2[j0 + s];
#pragma unroll
                for (int r = 0; r < 4; r++)
                    po[r] = fmaf(wv, gelu_exact(acc[r][s] + bv), po[r]);
            }
        }
#pragma unroll
        for (int off = 8; off; off >>= 1) {
#pragma unroll
            for (int r = 0; r < 4; r++)
                po[r] += __shfl_down_sync(0xffffffffu, po[r], off);
        }
        if (tx == 0) {
#pragma unroll
            for (int r = 0; r < 4; r++) out[p0g + p0 + r] = po[r] + qb;
        }
        __syncthreads();
    }
}

// ---------------- host launcher ----------------
extern "C" void kernel_launch(void* const* d_in, const int* in_sizes, int n_in,
                              void* d_out, int out_size) {
    const float* x_in   = (const float*)d_in[0];
    const float* p_w    = (const float*)d_in[1];
    const float* p_b    = (const float*)d_in[2];
    const float* W_LC   = (const float*)d_in[3];
    const float* W_LR   = (const float*)d_in[4];
    const float* mlp_w1 = (const float*)d_in[5];
    const float* mlp_b1 = (const float*)d_in[6];
    const float* mlp_w2 = (const float*)d_in[7];
    const float* mlp_b2 = (const float*)d_in[8];
    const float* w_w    = (const float*)d_in[9];
    const float* w_b    = (const float*)d_in[10];
    const float* q_w1   = (const float*)d_in[11];
    const float* q_b1   = (const float*)d_in[12];
    const float* q_w2   = (const float*)d_in[13];
    const float* q_b2   = (const float*)d_in[14];
    float* out = (float*)d_out;

    const int FUSE_SMEM = FUSE_SMEMF * 4;               // 84480 B
    const int QMLP_SMEM = (64 * 260 + 4096) * 4;        // 82944 B
    cudaFuncSetAttribute(fuse_k, cudaFuncAttributeMaxDynamicSharedMemorySize, FUSE_SMEM);
    cudaFuncSetAttribute(qmlp_k, cudaFuncAttributeMaxDynamicSharedMemorySize, QMLP_SMEM);

    init_tw_k<<<1, 256>>>();
    transpose_k<<<dim3(3, 128, NLAY),  dim3(32, 8)>>>(W_LC, 4096, 96,  0);
    transpose_k<<<dim3(31, 128, NLAY), dim3(32, 8)>>>(W_LR, 4096, 968, 1);

    lift_k<<<NPTS / 64, 256>>>(x_in, p_w, p_b);

    for (int l = 0; l < NLAY; l++) {
        fwdz_k<<<BB * S1D * S2D / 8, 256>>>();
        fwdy_k<<<BB * S2D * TTD, 96>>>();
        fwdx_k<<<BB * MMD * TTD, 96>>>();
        mix_k <<<MMD * MMD * TTD, 128>>>(l, mlp_w1 + l * 4096);
        invy_k<<<BB * MMD * TTD, 256>>>();
        invx_k<<<BB * S1D * TTD, 256>>>();
        fuse_k<<<592, 256, FUSE_SMEM>>>(
            mlp_b1 + l * 64,
            mlp_w2 + l * 4096, mlp_b2 + l * 64,
            w_w + l * 4096,    w_b + l * 64,
            (l < NLAY - 1) ? 1 : 0);
    }

    qmlp_k<<<592, 256, QMLP_SMEM>>>(q_w1, q_b1, q_w2, q_b2, out);
}